// round 15
// baseline (speedup 1.0000x reference)
#include <cuda_runtime.h>
#include <cuda_bf16.h>
#include <math.h>
#include <cstdint>

#define TTOK 49152      // total tokens = 2*6*64*64
#define NWIN 384

// ---------------- scratch (device globals; no allocations allowed) ----------
__device__ float g_qkv_s[TTOK*576];     // qkv fp32 (self)
__device__ float g_qkv_m[TTOK*576];     // qkv fp32 (mutual)
__device__ float g_attnbuf[TTOK*192];   // proj output (window order)
__device__ float g_pos[64*192];
__device__ __nv_bfloat16 g_bmh[192*8*128*128]; // combined mask+bias bf16 [mw][h][q][k]
__device__ __nv_bfloat16 g_mmh[192*64*64];     // mask quadrant bf16 [mw][q][k]
__device__ int   g_cnt[8];
__device__ int   g_gidx[8*TTOK];
__device__ float g_gw[8*TTOK];
__device__ int   g_grank[8*TTOK];
__device__ float g_contrib0[TTOK*192];
__device__ float g_contrib1[TTOK*192];
// bf16 activation buffers for tensor-core GEMMs
__device__ __nv_bfloat16 g_xw_bf[TTOK*192];
__device__ __nv_bfloat16 g_xm_bf[TTOK*192];
__device__ __nv_bfloat16 g_xout_bf[TTOK*384];
__device__ __nv_bfloat16 g_xn2_bf[TTOK*192];
__device__ __nv_bfloat16 g_hbuf[(size_t)8*TTOK*384];
// transposed bf16 weights [N][K]
__device__ __nv_bfloat16 g_wt_qs[576*192];
__device__ __nv_bfloat16 g_wt_qm[576*192];
__device__ __nv_bfloat16 g_wt_p [192*384];
__device__ __nv_bfloat16 g_wt_w1[8*384*192];
__device__ __nv_bfloat16 g_wt_w2[8*192*384];

// ---------------- helpers ------------------------------------------------
typedef unsigned long long ull;
__device__ __forceinline__ float warpsum_all(float v) {
    #pragma unroll
    for (int o = 16; o; o >>= 1) v += __shfl_xor_sync(0xffffffffu, v, o);
    return v;
}
__device__ __forceinline__ uint32_t smem_u32(const void* p) {
    uint32_t a;
    asm("{ .reg .u64 t; cvta.to.shared.u64 t, %1; cvt.u32.u64 %0, t; }" : "=r"(a) : "l"(p));
    return a;
}
__device__ __forceinline__ void ldsm_x4(uint32_t& r0, uint32_t& r1, uint32_t& r2,
                                        uint32_t& r3, uint32_t addr) {
    asm volatile("ldmatrix.sync.aligned.m8n8.x4.shared.b16 {%0,%1,%2,%3}, [%4];"
                 : "=r"(r0), "=r"(r1), "=r"(r2), "=r"(r3) : "r"(addr));
}
__device__ __forceinline__ void ldsm_x4_t(uint32_t& r0, uint32_t& r1, uint32_t& r2,
                                          uint32_t& r3, uint32_t addr) {
    asm volatile("ldmatrix.sync.aligned.m8n8.x4.trans.shared.b16 {%0,%1,%2,%3}, [%4];"
                 : "=r"(r0), "=r"(r1), "=r"(r2), "=r"(r3) : "r"(addr));
}
__device__ __forceinline__ void mma16816(float* c, uint32_t a0, uint32_t a1,
                                         uint32_t a2, uint32_t a3,
                                         uint32_t b0, uint32_t b1) {
    asm volatile("mma.sync.aligned.m16n8k16.row.col.f32.bf16.bf16.f32 "
        "{%0,%1,%2,%3}, {%4,%5,%6,%7}, {%8,%9}, {%0,%1,%2,%3};"
        : "+f"(c[0]), "+f"(c[1]), "+f"(c[2]), "+f"(c[3])
        : "r"(a0), "r"(a1), "r"(a2), "r"(a3), "r"(b0), "r"(b1));
}
__device__ __forceinline__ void cp16(uint32_t dst, const void* src, bool v) {
    asm volatile("cp.async.cg.shared.global [%0], [%1], 16, %2;"
                 :: "r"(dst), "l"(src), "r"(v ? 16u : 0u));
}
#define CP_COMMIT() asm volatile("cp.async.commit_group;")
#define CP_WAIT1()  asm volatile("cp.async.wait_group 1;")
#define CP_WAIT0()  asm volatile("cp.async.wait_group 0;")
#define SMEM_SWZ(o) ((o) ^ (((o) >> 3) & 0x70))
#define SMEM_SWZ64(o) ((o) ^ (((o) >> 3) & 0x30))

__device__ __forceinline__ uint32_t bf2(float x, float y) {
    __nv_bfloat162 t = __floats2bfloat162_rn(x, y);
    return *reinterpret_cast<uint32_t*>(&t);
}

// ---- 128x64 warp-tile MMA over one 64-K chunk (8 warps: 4m x 2n) ----------
__device__ __forceinline__ void mma_tile(uint32_t aB, uint32_t bB,
                                         float (&c)[2][4][4], int wm, int wn, int lane) {
    int g = lane >> 3, l7 = lane & 7;
    #pragma unroll
    for (int ks = 0; ks < 4; ks++) {
        uint32_t a[2][4];
        #pragma unroll
        for (int mi = 0; mi < 2; mi++) {
            int r = wm*32 + mi*16 + ((g & 1) << 3) + l7;
            int kb = ks*32 + ((g >> 1) << 4);
            ldsm_x4(a[mi][0], a[mi][1], a[mi][2], a[mi][3],
                    aB + SMEM_SWZ((uint32_t)(r*128 + kb)));
        }
        uint32_t b[4][2];
        #pragma unroll
        for (int np = 0; np < 2; np++) {
            int r = wn*32 + np*16 + ((g >> 1) << 3) + l7;
            int kb = ks*32 + ((g & 1) << 4);
            uint32_t r0, r1, r2, r3;
            ldsm_x4(r0, r1, r2, r3, bB + SMEM_SWZ((uint32_t)(r*128 + kb)));
            b[np*2][0] = r0;   b[np*2][1] = r1;
            b[np*2+1][0] = r2; b[np*2+1][1] = r3;
        }
        #pragma unroll
        for (int mi = 0; mi < 2; mi++)
            #pragma unroll
            for (int nj = 0; nj < 4; nj++)
                mma16816(c[mi][nj], a[mi][0], a[mi][1], a[mi][2], a[mi][3],
                         b[nj][0], b[nj][1]);
    }
}

// ---- 128x128 wide warp-tile MMA (8 warps: 4m x 2n, 64 n-cols per warp) -----
__device__ __forceinline__ void mma_tile_w(uint32_t aB, uint32_t bB,
                                           float (&c)[2][8][4], int wm, int wn, int lane) {
    int g = lane >> 3, l7 = lane & 7;
    #pragma unroll
    for (int ks = 0; ks < 4; ks++) {
        uint32_t a[2][4];
        #pragma unroll
        for (int mi = 0; mi < 2; mi++) {
            int r = wm*32 + mi*16 + ((g & 1) << 3) + l7;
            int kb = ks*32 + ((g >> 1) << 4);
            ldsm_x4(a[mi][0], a[mi][1], a[mi][2], a[mi][3],
                    aB + SMEM_SWZ((uint32_t)(r*128 + kb)));
        }
        uint32_t b[8][2];
        #pragma unroll
        for (int np = 0; np < 4; np++) {
            int r = wn*64 + np*16 + ((g >> 1) << 3) + l7;
            int kb = ks*32 + ((g & 1) << 4);
            uint32_t r0, r1, r2, r3;
            ldsm_x4(r0, r1, r2, r3, bB + SMEM_SWZ((uint32_t)(r*128 + kb)));
            b[np*2][0] = r0;   b[np*2][1] = r1;
            b[np*2+1][0] = r2; b[np*2+1][1] = r3;
        }
        #pragma unroll
        for (int mi = 0; mi < 2; mi++)
            #pragma unroll
            for (int nj = 0; nj < 8; nj++)
                mma16816(c[mi][nj], a[mi][0], a[mi][1], a[mi][2], a[mi][3],
                         b[nj][0], b[nj][1]);
    }
}

// ================= HMMA flash attention, register-resident P ================
// Block = (win, head), 256 threads / 8 warps; warp w owns S rows w*16..w*16+15.
// smem: sQ 16K | sK 16K | sV 8K (128x64B, SW64).
template<int MUT>
__global__ __launch_bounds__(256, 2) void attn_mma() {
    extern __shared__ uint8_t sm[];
    uint32_t base = (smem_u32(sm) + 1023u) & ~1023u;
    uint8_t* smp = sm + (base - smem_u32(sm));
    const uint32_t sQ = base, sK = base + 16384, sV = base + 32768;

    int tid = threadIdx.x, wid = tid >> 5, lane = tid & 31;
    int win = blockIdx.x >> 3, h = blockIdx.x & 7;
    const float* qkv = MUT ? g_qkv_m : g_qkv_s;
    const float SC = 0.20412414523193154f;   // 24^-0.5

    // ---------- staging ----------
    if (tid < 128) {
        int r = tid;
        int qrow = MUT ? ((r + 64) & 127) : r;
        const float4* qp = reinterpret_cast<const float4*>(
            qkv + (size_t)(win*128 + qrow)*576 + h*24);
        uint32_t w[12];
        #pragma unroll
        for (int i = 0; i < 6; i++) {
            float4 a = qp[i];
            w[2*i]   = bf2(a.x*SC, a.y*SC);
            w[2*i+1] = bf2(a.z*SC, a.w*SC);
        }
        *reinterpret_cast<uint4*>(smp + SMEM_SWZ((uint32_t)(r*128 + 0)))  = make_uint4(w[0],w[1],w[2],w[3]);
        *reinterpret_cast<uint4*>(smp + SMEM_SWZ((uint32_t)(r*128 + 16))) = make_uint4(w[4],w[5],w[6],w[7]);
        *reinterpret_cast<uint4*>(smp + SMEM_SWZ((uint32_t)(r*128 + 32))) = make_uint4(w[8],w[9],w[10],w[11]);
        *reinterpret_cast<uint4*>(smp + SMEM_SWZ((uint32_t)(r*128 + 48))) = make_uint4(0,0,0,0);
        // V natural rows: sV[key][dim], 64B rows (24 dims + 8 zero pad), SW64
        const float4* vp = reinterpret_cast<const float4*>(
            qkv + (size_t)(win*128 + r)*576 + h*24 + 384);
        uint32_t v[12];
        #pragma unroll
        for (int i = 0; i < 6; i++) {
            float4 a = vp[i];
            v[2*i]   = bf2(a.x, a.y);
            v[2*i+1] = bf2(a.z, a.w);
        }
        uint8_t* vb = smp + 32768;
        *reinterpret_cast<uint4*>(vb + SMEM_SWZ64((uint32_t)(r*64 + 0)))  = make_uint4(v[0],v[1],v[2],v[3]);
        *reinterpret_cast<uint4*>(vb + SMEM_SWZ64((uint32_t)(r*64 + 16))) = make_uint4(v[4],v[5],v[6],v[7]);
        *reinterpret_cast<uint4*>(vb + SMEM_SWZ64((uint32_t)(r*64 + 32))) = make_uint4(v[8],v[9],v[10],v[11]);
        *reinterpret_cast<uint4*>(vb + SMEM_SWZ64((uint32_t)(r*64 + 48))) = make_uint4(0,0,0,0);
    } else {
        int r = tid - 128;
        const float4* kp = reinterpret_cast<const float4*>(
            qkv + (size_t)(win*128 + r)*576 + h*24 + 192);
        uint32_t w[12];
        #pragma unroll
        for (int i = 0; i < 6; i++) {
            float4 a = kp[i];
            w[2*i]   = bf2(a.x, a.y);
            w[2*i+1] = bf2(a.z, a.w);
        }
        uint8_t* kbp = smp + 16384;
        *reinterpret_cast<uint4*>(kbp + SMEM_SWZ((uint32_t)(r*128 + 0)))  = make_uint4(w[0],w[1],w[2],w[3]);
        *reinterpret_cast<uint4*>(kbp + SMEM_SWZ((uint32_t)(r*128 + 16))) = make_uint4(w[4],w[5],w[6],w[7]);
        *reinterpret_cast<uint4*>(kbp + SMEM_SWZ((uint32_t)(r*128 + 32))) = make_uint4(w[8],w[9],w[10],w[11]);
        *reinterpret_cast<uint4*>(kbp + SMEM_SWZ((uint32_t)(r*128 + 48))) = make_uint4(0,0,0,0);
    }
    __syncthreads();

    int g = lane >> 3, l7 = lane & 7;
    int qr = lane >> 2, qc = (lane & 3) * 2;
    int r0 = wid * 16;

    // ---------- S = Q @ K^T : warp owns rows r0..r0+15, all 128 cols ----------
    float c[16][4] = {};
    #pragma unroll
    for (int ks = 0; ks < 2; ks++) {
        uint32_t a0, a1, a2, a3;
        int ar = r0 + ((g & 1) << 3) + l7;
        int akb = ks*32 + ((g >> 1) << 4);
        ldsm_x4(a0, a1, a2, a3, sQ + SMEM_SWZ((uint32_t)(ar*128 + akb)));
        #pragma unroll
        for (int np = 0; np < 8; np++) {
            int r = np*16 + ((g >> 1) << 3) + l7;
            int kb = ks*32 + ((g & 1) << 4);
            uint32_t b0, b1, b2, b3;
            ldsm_x4(b0, b1, b2, b3, sK + SMEM_SWZ((uint32_t)(r*128 + kb)));
            mma16816(c[2*np],   a0, a1, a2, a3, b0, b1);
            mma16816(c[2*np+1], a0, a1, a2, a3, b2, b3);
        }
    }

    // ---------- softmax in-register, pack P to A-fragments ----------
    const __nv_bfloat16* bm = g_bmh + ((size_t)((win % 192)*8 + h))*16384;
    const __nv_bfloat16* mm = g_mmh + (size_t)(win % 192)*4096;
    int row0q = r0 + qr, row1q = r0 + 8 + qr;
    float sum0 = 0.f, sum1 = 0.f;
    uint32_t pa[8][4];
    #pragma unroll
    for (int nj = 0; nj < 16; nj++) {
        int col = nj*8 + qc;
        float bx0, by0, bx1, by1;
        if (MUT) {
            float2 m0 = __bfloat1622float2(*reinterpret_cast<const __nv_bfloat162*>(
                mm + (row0q & 63)*64 + (col & 63)));
            float2 m1 = __bfloat1622float2(*reinterpret_cast<const __nv_bfloat162*>(
                mm + (row1q & 63)*64 + (col & 63)));
            float g0 = ((row0q ^ col) & 64) ? -10000.f : 0.f;
            float g1 = ((row1q ^ col) & 64) ? -10000.f : 0.f;
            bx0 = m0.x + g0; by0 = m0.y + g0;
            bx1 = m1.x + g1; by1 = m1.y + g1;
        } else {
            float2 b0 = __bfloat1622float2(*reinterpret_cast<const __nv_bfloat162*>(
                bm + row0q*128 + col));
            float2 b1 = __bfloat1622float2(*reinterpret_cast<const __nv_bfloat162*>(
                bm + row1q*128 + col));
            bx0 = b0.x; by0 = b0.y;
            bx1 = b1.x; by1 = b1.y;
        }
        float p00 = __expf(c[nj][0] + bx0);
        float p01 = __expf(c[nj][1] + by0);
        float p10 = __expf(c[nj][2] + bx1);
        float p11 = __expf(c[nj][3] + by1);
        sum0 += p00 + p01;
        sum1 += p10 + p11;
        int kt = nj >> 1, half = (nj & 1) << 1;
        pa[kt][half + 0] = bf2(p00, p01);
        pa[kt][half + 1] = bf2(p10, p11);
    }
    sum0 += __shfl_xor_sync(0xffffffffu, sum0, 1);
    sum0 += __shfl_xor_sync(0xffffffffu, sum0, 2);
    sum1 += __shfl_xor_sync(0xffffffffu, sum1, 1);
    sum1 += __shfl_xor_sync(0xffffffffu, sum1, 2);

    // ---------- O = P @ V : A from registers, B via ldmatrix.trans on sV ----
    float o[3][4] = {};
    #pragma unroll
    for (int kt = 0; kt < 8; kt++) {
        int krow = kt*16 + ((g & 1) << 3) + l7;
        uint32_t b0, b1, b2, b3, d0, d1, d2, d3;
        ldsm_x4_t(b0, b1, b2, b3, sV + SMEM_SWZ64((uint32_t)(krow*64 + ((g >> 1) << 4))));
        ldsm_x4_t(d0, d1, d2, d3, sV + SMEM_SWZ64((uint32_t)(krow*64 + 32 + ((g >> 1) << 4))));
        mma16816(o[0], pa[kt][0], pa[kt][1], pa[kt][2], pa[kt][3], b0, b1);
        mma16816(o[1], pa[kt][0], pa[kt][1], pa[kt][2], pa[kt][3], b2, b3);
        mma16816(o[2], pa[kt][0], pa[kt][1], pa[kt][2], pa[kt][3], d0, d1);
    }

    // ---------- epilogue: divide by register row sums, store bf16 ----------
    int coff = MUT ? 0 : 192;
    float inv0 = 1.f / sum0, inv1 = 1.f / sum1;
    #pragma unroll
    for (int hh = 0; hh < 2; hh++) {
        int row = r0 + hh*8 + qr;
        float inv = hh ? inv1 : inv0;
        __nv_bfloat16* ob = g_xout_bf + (size_t)(win*128 + row)*384 + coff + h*24;
        #pragma unroll
        for (int nj = 0; nj < 3; nj++) {
            float v0 = o[nj][2*hh]   * inv;
            float v1 = o[nj][2*hh+1] * inv;
            *reinterpret_cast<uint32_t*>(ob + nj*8 + qc) = bf2(v0, v1);
        }
    }
}

// ---- shared mode-0 GEMM core: C fp32 = A @ Bt^T + bias ---------------------
__device__ __forceinline__ void gemm_core0(
        const __nv_bfloat16* __restrict__ A,
        const __nv_bfloat16* __restrict__ Bt,
        const float* __restrict__ bias,
        float* __restrict__ Cf, int K, int ldC, uint8_t* dyn_raw) {
    int tid = threadIdx.x, wid = tid >> 5, lane = tid & 31;
    int wm = wid >> 1, wn = wid & 1;
    int row0 = blockIdx.x * 128, col0 = blockIdx.y * 64;

    uint32_t aBase = (smem_u32(dyn_raw) + 1023u) & ~1023u;
    uint32_t bBase = aBase + 32768;

    int srow = tid >> 3, c16 = tid & 7;
    const __nv_bfloat16* arp[4]; uint32_t aOff[4];
    #pragma unroll
    for (int i = 0; i < 4; i++) {
        int r = i*32 + srow;
        aOff[i] = SMEM_SWZ((uint32_t)(r*128 + c16*16));
        arp[i] = A + (size_t)(row0 + r)*K + c16*8;
    }
    const __nv_bfloat16* brp[2]; uint32_t bOff[2];
    #pragma unroll
    for (int i = 0; i < 2; i++) {
        int r = i*32 + srow;
        bOff[i] = SMEM_SWZ((uint32_t)(r*128 + c16*16));
        brp[i] = Bt + (size_t)(col0 + r)*K + c16*8;
    }

    float c[2][4][4] = {};
    int nch = K >> 6;

    #pragma unroll
    for (int i = 0; i < 4; i++) cp16(aBase + aOff[i], arp[i], true);
    #pragma unroll
    for (int i = 0; i < 2; i++) cp16(bBase + bOff[i], brp[i], true);
    CP_COMMIT();

    for (int ic = 0; ic < nch; ic++) {
        if (ic + 1 < nch) {
            int buf = (ic + 1) & 1, kc = (ic + 1) << 6;
            #pragma unroll
            for (int i = 0; i < 4; i++)
                cp16(aBase + buf*16384 + aOff[i], arp[i] + kc, true);
            #pragma unroll
            for (int i = 0; i < 2; i++)
                cp16(bBase + buf*8192 + bOff[i], brp[i] + kc, true);
            CP_COMMIT();
            CP_WAIT1();
        } else {
            CP_WAIT0();
        }
        __syncthreads();
        mma_tile(aBase + (ic & 1)*16384, bBase + (ic & 1)*8192, c, wm, wn, lane);
        __syncthreads();
    }

    int qr = lane >> 2, qc = (lane & 3) * 2;
    #pragma unroll
    for (int mi = 0; mi < 2; mi++) {
        #pragma unroll
        for (int h = 0; h < 2; h++) {
            int lr = wm*32 + mi*16 + h*8 + qr;
            #pragma unroll
            for (int nj = 0; nj < 4; nj++) {
                int col = col0 + wn*32 + nj*8 + qc;
                size_t crow = (size_t)(row0 + lr)*ldC + col;
                *reinterpret_cast<float2*>(Cf + crow) =
                    make_float2(c[mi][nj][2*h] + bias[col],
                                c[mi][nj][2*h+1] + bias[col+1]);
            }
        }
    }
}

// ---- merged QKV GEMM: z=0 self, z=1 mutual ----------------------------------
__global__ __launch_bounds__(256, 3) void gemm_qkv(const float* __restrict__ qsb,
                                                   const float* __restrict__ qmb) {
    extern __shared__ uint8_t dyn_raw[];
    if (blockIdx.z == 0)
        gemm_core0(g_xw_bf, g_wt_qs, qsb, g_qkv_s, 192, 576, dyn_raw);
    else
        gemm_core0(g_xm_bf, g_wt_qm, qmb, g_qkv_m, 192, 576, dyn_raw);
}

// ---- proj GEMM ---------------------------------------------------------------
__global__ __launch_bounds__(256, 3) void gemm_proj(
        const __nv_bfloat16* __restrict__ A, const __nv_bfloat16* __restrict__ Bt,
        const float* __restrict__ bias, float* __restrict__ Cf, int K, int ldC) {
    extern __shared__ uint8_t dyn_raw[];
    gemm_core0(A, Bt, bias, Cf, K, ldC, dyn_raw);
}

// ======= MoE FC1: gather + gelu -> g_hbuf, wide 128x128 tile, K=192 =========
__global__ __launch_bounds__(256) void gemm_moe1(const float* __restrict__ b1) {
    extern __shared__ uint8_t dyn_raw[];
    __shared__ int s_tok[128];
    int tid = threadIdx.x, wid = tid >> 5, lane = tid & 31;
    int wm = wid >> 1, wn = wid & 1;
    int row0 = blockIdx.x * 128, col0 = blockIdx.y * 128;
    int e = blockIdx.z;
    int cnt = g_cnt[e];
    if (row0 >= cnt) return;
    const __nv_bfloat16* W1te = g_wt_w1 + (size_t)e*73728;
    const float* b1e = b1 + e*384;

    if (tid < 128) {
        int slot = row0 + tid;
        s_tok[tid] = (slot < cnt) ? g_gidx[e*TTOK + slot] : -1;
    }
    __syncthreads();

    uint32_t aBase = (smem_u32(dyn_raw) + 1023u) & ~1023u;
    uint32_t bBase = aBase + 32768;

    int srow = tid >> 3, c16 = tid & 7;
    const __nv_bfloat16* arp[4]; bool av[4]; uint32_t off[4];
    const __nv_bfloat16* brp[4];
    #pragma unroll
    for (int i = 0; i < 4; i++) {
        int r = i*32 + srow;
        off[i] = SMEM_SWZ((uint32_t)(r*128 + c16*16));
        int tk = s_tok[r];
        av[i] = (tk >= 0);
        arp[i] = g_xn2_bf + (size_t)(av[i] ? tk : 0)*192 + c16*8;
        brp[i] = W1te + (size_t)(col0 + r)*192 + c16*8;
    }

    float c[2][8][4] = {};

    #pragma unroll
    for (int i = 0; i < 4; i++) cp16(aBase + off[i], arp[i], av[i]);
    #pragma unroll
    for (int i = 0; i < 4; i++) cp16(bBase + off[i], brp[i], true);
    CP_COMMIT();

    for (int ic = 0; ic < 3; ic++) {
        if (ic + 1 < 3) {
            int buf = (ic + 1) & 1, kc = (ic + 1) << 6;
            #pragma unroll
            for (int i = 0; i < 4; i++)
                cp16(aBase + buf*16384 + off[i], arp[i] + kc, av[i]);
            #pragma unroll
            for (int i = 0; i < 4; i++)
                cp16(bBase + buf*16384 + off[i], brp[i] + kc, true);
            CP_COMMIT();
            CP_WAIT1();
        } else {
            CP_WAIT0();
        }
        __syncthreads();
        mma_tile_w(aBase + (ic & 1)*16384, bBase + (ic & 1)*16384, c, wm, wn, lane);
        __syncthreads();
    }

    int qr = lane >> 2, qc = (lane & 3) * 2;
    #pragma unroll
    for (int mi = 0; mi < 2; mi++) {
        #pragma unroll
        for (int h = 0; h < 2; h++) {
            int lr = wm*32 + mi*16 + h*8 + qr;
            if (s_tok[lr] >= 0) {
                size_t hrow = ((size_t)e*TTOK + row0 + lr)*384;
                #pragma unroll
                for (int nj = 0; nj < 8; nj++) {
                    int col = col0 + wn*64 + nj*8 + qc;
                    float h0 = c[mi][nj][2*h]   + b1e[col];
                    float h1 = c[mi][nj][2*h+1] + b1e[col+1];
                    h0 = h0 * normcdff(h0);
                    h1 = h1 * normcdff(h1);
                    *reinterpret_cast<uint32_t*>(g_hbuf + hrow + col) = bf2(h0, h1);
                }
            }
        }
    }
}

// ======= MoE FC2: weighted scatter -> contrib buffers, K=384 ================
__global__ __launch_bounds__(256, 3) void gemm_moe2(const float* __restrict__ b2) {
    extern __shared__ uint8_t dyn_raw[];
    __shared__ int s_tok[128]; __shared__ float s_wgt[128]; __shared__ int s_rnk[128];

    int tid = threadIdx.x, wid = tid >> 5, lane = tid & 31;
    int wm = wid >> 1, wn = wid & 1;
    int row0 = blockIdx.x * 128, col0 = blockIdx.y * 64;
    int e = blockIdx.z;
    int cnt = g_cnt[e];
    if (row0 >= cnt) return;
    const __nv_bfloat16* Bte = g_wt_w2 + (size_t)e*73728;
    const float* be = b2 + e*192;
    const __nv_bfloat16* Ae = g_hbuf + (size_t)e*TTOK*384;

    if (tid < 128) {
        int slot = row0 + tid;
        if (slot < cnt) {
            s_tok[tid] = g_gidx[e*TTOK + slot];
            s_wgt[tid] = g_gw[e*TTOK + slot];
            s_rnk[tid] = g_grank[e*TTOK + slot];
        } else s_tok[tid] = -1;
    }
    __syncthreads();

    uint32_t aBase = (smem_u32(dyn_raw) + 1023u) & ~1023u;
    uint32_t bBase = aBase + 32768;

    int srow = tid >> 3, c16 = tid & 7;
    const __nv_bfloat16* arp[4]; bool av[4]; uint32_t aOff[4];
    #pragma unroll
    for (int i = 0; i < 4; i++) {
        int r = i*32 + srow;
        aOff[i] = SMEM_SWZ((uint32_t)(r*128 + c16*16));
        av[i] = (row0 + r < cnt);
        arp[i] = Ae + (size_t)(av[i] ? (row0 + r) : 0)*384 + c16*8;
    }
    const __nv_bfloat16* brp[2]; uint32_t bOff[2];
    #pragma unroll
    for (int i = 0; i < 2; i++) {
        int r = i*32 + srow;
        bOff[i] = SMEM_SWZ((uint32_t)(r*128 + c16*16));
        brp[i] = Bte + (size_t)(col0 + r)*384 + c16*8;
    }

    float c[2][4][4] = {};

    #pragma unroll
    for (int i = 0; i < 4; i++) cp16(aBase + aOff[i], arp[i], av[i]);
    #pragma unroll
    for (int i = 0; i < 2; i++) cp16(bBase + bOff[i], brp[i], true);
    CP_COMMIT();

    for (int ic = 0; ic < 6; ic++) {
        if (ic + 1 < 6) {
            int buf = (ic + 1) & 1, kc = (ic + 1) << 6;
            #pragma unroll
            for (int i = 0; i < 4; i++)
                cp16(aBase + buf*16384 + aOff[i], arp[i] + kc, av[i]);
            #pragma unroll
            for (int i = 0; i < 2; i++)
                cp16(bBase + buf*8192 + bOff[i], brp[i] + kc, true);
            CP_COMMIT();
            CP_WAIT1();
        } else {
            CP_WAIT0();
        }
        __syncthreads();
        mma_tile(aBase + (ic & 1)*16384, bBase + (ic & 1)*8192, c, wm, wn, lane);
        __syncthreads();
    }

    int qr = lane >> 2, qc = (lane & 3) * 2;
    #pragma unroll
    for (int mi = 0; mi < 2; mi++) {
        #pragma unroll
        for (int h = 0; h < 2; h++) {
            int lr = wm*32 + mi*16 + h*8 + qr;
            int tk = s_tok[lr];
            if (tk >= 0) {
                float w = s_wgt[lr];
                float* dst = (s_rnk[lr] == 0) ? g_contrib0 : g_contrib1;
                #pragma unroll
                for (int nj = 0; nj < 4; nj++) {
                    int col = col0 + wn*32 + nj*8 + qc;
                    *reinterpret_cast<float2*>(dst + (size_t)tk*192 + col) =
                        make_float2(w*(c[mi][nj][2*h]   + be[col]),
                                    w*(c[mi][nj][2*h+1] + be[col+1]));
                }
            }
        }
    }
}

// ---- merged prep: transpose (0-359) | bmh (360-1895) | mmh (1896-2087) | pos (2088)
__global__ __launch_bounds__(256) void k_prep_all(
        const float* __restrict__ qs, const float* __restrict__ qm,
        const float* __restrict__ pw, const float* __restrict__ W1,
        const float* __restrict__ W2, const float* __restrict__ rpb,
        const float* __restrict__ mask) {
    __shared__ float tile[64][65];
    int bid = blockIdx.x;
    if (bid < 360) {
        const float* src; __nv_bfloat16* dst; int K, N, tk, tn;
        if (bid < 27)       { src = qs; dst = g_wt_qs; K = 192; N = 576; tk = bid/9; tn = bid%9; }
        else if (bid < 54)  { int j = bid-27; src = qm; dst = g_wt_qm; K = 192; N = 576; tk = j/9; tn = j%9; }
        else if (bid < 72)  { int j = bid-54; src = pw; dst = g_wt_p;  K = 384; N = 192; tk = j/3; tn = j%3; }
        else if (bid < 216) { int j = bid-72;  int e = j/18; j %= 18;
                              src = W1 + (size_t)e*73728; dst = g_wt_w1 + (size_t)e*73728;
                              K = 192; N = 384; tk = j/6; tn = j%6; }
        else                { int j = bid-216; int e = j/18; j %= 18;
                              src = W2 + (size_t)e*73728; dst = g_wt_w2 + (size_t)e*73728;
                              K = 384; N = 192; tk = j/3; tn = j%3; }
        int rr = threadIdx.x >> 6, cc = threadIdx.x & 63;
        #pragma unroll 4
        for (int i = 0; i < 16; i++) {
            int r = rr + 4*i;
            tile[r][cc] = src[(size_t)(tk*64 + r)*N + tn*64 + cc];
        }
        __syncthreads();
        #pragma unroll 4
        for (int i = 0; i < 16; i++) {
            int r = rr + 4*i;
            dst[(size_t)(tn*64 + r)*K + tk*64 + cc] = __float2bfloat16_rn(tile[cc][r]);
        }
    } else if (bid < 1896) {
        // combined mask+bias bf16 table: one block per (mw, h)
        int idx = bid - 360;
        int mw = idx >> 3, h = idx & 7;
        const float* mrow = mask + (size_t)mw*16384;
        __nv_bfloat16* dst = g_bmh + (size_t)idx*16384;
        for (int e = threadIdx.x; e < 8192; e += 256) {
            int q = e >> 6, k2 = (e & 63)*2;
            int dn = q >> 6, hn = (q >> 3) & 7, wn = q & 7;
            float v[2];
            #pragma unroll
            for (int j = 0; j < 2; j++) {
                int k = k2 + j;
                int dm = k >> 6, hm = (k >> 3) & 7, wm = k & 7;
                int rp = (dn - dm + 1)*225 + (hn - hm + 7)*15 + (wn - wm + 7);
                v[j] = mrow[q*128 + k] + rpb[rp*8 + h];
            }
            *reinterpret_cast<uint32_t*>(dst + q*128 + k2) = bf2(v[0], v[1]);
        }
    } else if (bid < 2088) {
        // mask quadrant bf16: one block per mw
        int mw = bid - 1896;
        const float* mrow = mask + (size_t)mw*16384;
        __nv_bfloat16* dst = g_mmh + (size_t)mw*4096;
        for (int e = threadIdx.x; e < 2048; e += 256) {
            int q = e >> 5, k2 = (e & 31)*2;
            float v0 = mrow[q*128 + k2], v1 = mrow[q*128 + k2 + 1];
            *reinterpret_cast<uint32_t*>(dst + q*64 + k2) = bf2(v0, v1);
        }
    } else {
        int c = threadIdx.x;
        if (c >= 192) return;
        if (c < 8) g_cnt[c] = 0;
        const float TWO_PI = 6.283185307179586f;
        const float denom = 8.0f + 1e-6f;
        int f = (c < 96) ? c : c - 96;
        float expo = (float)(f & ~1) / 96.0f;
        float dt = powf(10000.0f, expo);
        for (int n = 0; n < 64; n++) {
            int i = n >> 3, j = n & 7;
            float base = (c < 96) ? (float)(i + 1) : (float)(j + 1);
            float v = base / denom * TWO_PI / dt;
            g_pos[n*192 + c] = (f & 1) ? cosf(v) : sinf(v);
        }
    }
}

// ---------------- LN1 + roll + window partition -> bf16 (warp per token) -----
__global__ __launch_bounds__(256) void ln_partition(const float* __restrict__ x,
                             const float* __restrict__ w1,
                             const float* __restrict__ b1) {
    int t = (blockIdx.x*blockDim.x + threadIdx.x) >> 5;
    int lane = threadIdx.x & 31;
    int win = t >> 7, n = t & 127;
    int b_  = win / 192; int rem = win % 192;
    int dd  = rem / 64;  int rem2 = rem % 64;
    int hh  = rem2 >> 3; int ww = rem2 & 7;
    int wd  = n >> 6, wh = (n >> 3) & 7, wwp = n & 7;
    int ds = dd*2 + wd, hs = hh*8 + wh, ws = ww*8 + wwp;
    int d = ds + 1; if (d >= 6) d -= 6;
    int h = (hs + 4) & 63;
    int w = (ws + 4) & 63;
    const float* xr = x + (size_t)(((b_*6 + d)*64 + h)*64 + w)*192;
    float v[6];
    float s1 = 0.f, s2 = 0.f;
    #pragma unroll
    for (int k = 0; k < 6; k++) {
        v[k] = xr[lane + 32*k];
        s1 += v[k]; s2 += v[k]*v[k];
    }
    s1 = warpsum_all(s1); s2 = warpsum_all(s2);
    float mu  = s1 * (1.f/192.f);
    float var = s2 * (1.f/192.f) - mu*mu;
    float rstd = rsqrtf(var + 1e-5f);
    const float* pr = g_pos + (n & 63)*192;
    #pragma unroll
    for (int k = 0; k < 6; k++) {
        int cc = lane + 32*k;
        float y = (v[k] - mu) * rstd * w1[cc] + b1[cc];
        g_xw_bf[(size_t)t*192 + cc] = __float2bfloat16_rn(y);
        g_xm_bf[(size_t)t*192 + cc] = __float2bfloat16_rn(y + pr[cc]);
    }
}

// --------- residual (writes out directly) + LN2 + gate top-2 -----------------
__global__ __launch_bounds__(256) void resid_gate(const float* __restrict__ x,
                           const float* __restrict__ n2w, const float* __restrict__ n2b,
                           const float* __restrict__ gw,  const float* __restrict__ gb,
                           float* __restrict__ out) {
    __shared__ float s_gw[8*192];
    for (int i = threadIdx.x; i < 1536; i += 256) {
        int j = i / 192, cc = i % 192;
        s_gw[i] = gw[cc*8 + j];
    }
    __syncthreads();
    int t = (blockIdx.x*blockDim.x + threadIdx.x) >> 5;
    int lane = threadIdx.x & 31;
    int b_ = t / 24576; int rrem = t % 24576;
    int d  = rrem / 4096; int r2 = rrem % 4096;
    int hh_ = r2 / 64; int ww_ = r2 % 64;
    int ds = d - 1; if (ds < 0) ds += 6;
    int hs = (hh_ + 60) & 63;
    int ws = (ww_ + 60) & 63;
    int dd = ds >> 1, wd = ds & 1;
    int hblk = hs >> 3, wh = hs & 7;
    int wblk = ws >> 3, wwp = ws & 7;
    int win = ((b_*3 + dd)*8 + hblk)*8 + wblk;
    int n = wd*64 + wh*8 + wwp;
    const float* ar = g_attnbuf + (size_t)(win*128 + n)*192;
    const float* xr = x + (size_t)t*192;
    float v[6];
    float s1 = 0.f, s2 = 0.f;
    #pragma unroll
    for (int k = 0; k < 6; k++) {
        int cc = lane + 32*k;
        v[k] = xr[cc] + ar[cc];
        out[(size_t)t*192 + cc] = v[k];
        s1 += v[k]; s2 += v[k]*v[k];
    }
    s1 = warpsum_all(s1); s2 = warpsum_all(s2);
    float mu  = s1 * (1.f/192.f);
    float var = s2 * (1.f/192.f) - mu*mu;
    float rstd = rsqrtf(var + 1e-5f);
    float g[8] = {};
    #pragma unroll
    for (int k = 0; k < 6; k++) {
        int cc = lane + 32*k;
        float xn = (v[k] - mu) * rstd * n2w[cc] + n2b[cc];
        g_xn2_bf[(size_t)t*192 + cc] = __float2bfloat16_rn(xn);
        #pragma unroll
        for (int j = 0; j < 8; j++) g[j] = fmaf(xn, s_gw[j*192 + cc], g[j]);
    }
    #pragma unroll
    for (int j = 0; j < 8; j++) g[j] = warpsum_all(g[j]);
    if (lane == 0) {
        float L[8];
        #pragma unroll
        for (int j = 0; j < 8; j++) L[j] = g[j] + gb[j];
        int e0 = 0;
        #pragma unroll
        for (int j = 1; j < 8; j++) if (L[j] > L[e0]) e0 = j;
        int e1 = (e0 == 0) ? 1 : 0;
        #pragma unroll
        for (int j = 0; j < 8; j++) if (j != e0 && L[j] > L[e1]) e1 = j;
        float w0 = 1.f / (1.f + __expf(L[e1] - L[e0]));
        float w1 = 1.f - w0;
        int p0 = atomicAdd(&g_cnt[e0], 1);
        g_gidx[e0*TTOK + p0] = t; g_gw[e0*TTOK + p0] = w0; g_grank[e0*TTOK + p0] = 0;
        int p1 = atomicAdd(&g_cnt[e1], 1);
        g_gidx[e1*TTOK + p1] = t; g_gw[e1*TTOK + p1] = w1; g_grank[e1*TTOK + p1] = 1;
    }
}

// ---------------- finalize: out += contrib0 + contrib1 -----------------------
__global__ void finalize(float* __restrict__ out) {
    int i = blockIdx.x*blockDim.x + threadIdx.x;
    if (i < TTOK*48) {
        float4 a  = reinterpret_cast<const float4*>(out)[i];
        float4 c0 = reinterpret_cast<const float4*>(g_contrib0)[i];
        float4 c1 = reinterpret_cast<const float4*>(g_contrib1)[i];
        reinterpret_cast<float4*>(out)[i] =
            make_float4(a.x + c0.x + c1.x, a.y + c0.y + c1.y,
                        a.z + c0.z + c1.z, a.w + c0.w + c1.w);
    }
}

// ---------------- host launcher -----------------------------------------------
extern "C" void kernel_launch(void* const* d_in, const int* in_sizes, int n_in,
                              void* d_out, int out_size) {
    const float* x    = (const float*)d_in[0];
    const float* mask = (const float*)d_in[1];
    const float* n1w  = (const float*)d_in[2];
    const float* n1b  = (const float*)d_in[3];
    const float* qsw  = (const float*)d_in[4];
    const float* qsb  = (const float*)d_in[5];
    const float* qmw  = (const float*)d_in[6];
    const float* qmb  = (const float*)d_in[7];
    const float* rpb  = (const float*)d_in[8];
    const float* pw   = (const float*)d_in[9];
    const float* pb   = (const float*)d_in[10];
    const float* n2w  = (const float*)d_in[11];
    const float* n2b  = (const float*)d_in[12];
    const float* gw   = (const float*)d_in[13];
    const float* gb   = (const float*)d_in[14];
    const float* W1   = (const float*)d_in[15];
    const float* b1   = (const float*)d_in[16];
    const float* W2   = (const float*)d_in[17];
    const float* b2   = (const float*)d_in[18];
    float* out = (float*)d_out;

    const int DSMEM  = 50176;   // 48KB + align pad
    const int DSMEM1 = 66560;   // 64KB + align pad (wide FC1)
    const int ASMEM  = 41984;   // attn: 40KB tiles + align pad
    cudaFuncSetAttribute(gemm_qkv,    cudaFuncAttributeMaxDynamicSharedMemorySize, DSMEM);
    cudaFuncSetAttribute(gemm_proj,   cudaFuncAttributeMaxDynamicSharedMemorySize, DSMEM);
    cudaFuncSetAttribute(gemm_moe1,   cudaFuncAttributeMaxDynamicSharedMemorySize, DSMEM1);
    cudaFuncSetAttribute(gemm_moe2,   cudaFuncAttributeMaxDynamicSharedMemorySize, DSMEM);
    cudaFuncSetAttribute(attn_mma<0>, cudaFuncAttributeMaxDynamicSharedMemorySize, ASMEM);
    cudaFuncSetAttribute(attn_mma<1>, cudaFuncAttributeMaxDynamicSharedMemorySize, ASMEM);

    void *p_xout, *p_attn, *p_wp;
    cudaGetSymbolAddress(&p_xout, g_xout_bf);
    cudaGetSymbolAddress(&p_attn, g_attnbuf);
    cudaGetSymbolAddress(&p_wp,   g_wt_p);

    k_prep_all<<<2089, 256>>>(qsw, qmw, pw, W1, W2, rpb, mask);
    ln_partition<<<6144, 256>>>(x, n1w, n1b);
    gemm_qkv<<<dim3(384, 9, 2), 256, DSMEM>>>(qsb, qmb);
    attn_mma<0><<<3072, 256, ASMEM>>>();                   // <- profiled slot
    attn_mma<1><<<3072, 256, ASMEM>>>();
    gemm_proj<<<dim3(384, 3), 256, DSMEM>>>((const __nv_bfloat16*)p_xout,
        (const __nv_bfloat16*)p_wp, pb, (float*)p_attn, 384, 192);
    resid_gate<<<6144, 256>>>(x, n2w, n2b, gw, gb, out);
    gemm_moe1<<<dim3(384, 3, 8), 256, DSMEM1>>>(b1);
    gemm_moe2<<<dim3(384, 3, 8), 256, DSMEM>>>(b2);
    finalize<<<9216, 256>>>(out);
}

// round 16
// speedup vs baseline: 1.0400x; 1.0400x over previous
#include <cuda_runtime.h>
#include <cuda_bf16.h>
#include <math.h>
#include <cstdint>

#define TTOK 49152      // total tokens = 2*6*64*64
#define NWIN 384

// ---------------- scratch (device globals; no allocations allowed) ----------
__device__ float g_qkv_s[TTOK*576];     // qkv fp32 (self)
__device__ float g_qkv_m[TTOK*576];     // qkv fp32 (mutual)
__device__ float g_attnbuf[TTOK*192];   // proj output (window order)
__device__ float g_pos[64*192];
__device__ __nv_bfloat16 g_bmh[8*8*128*128]; // combined mask+bias bf16 [sel][h][q][k]
__device__ __nv_bfloat16 g_mmh[8*64*64];     // mask quadrant bf16 [sel][q][k]
__device__ int   g_cnt[8];
__device__ int   g_gidx[8*TTOK];
__device__ float g_gw[8*TTOK];
__device__ int   g_grank[8*TTOK];
__device__ float g_contrib0[TTOK*192];
__device__ float g_contrib1[TTOK*192];
// bf16 activation buffers for tensor-core GEMMs
__device__ __nv_bfloat16 g_xw_bf[TTOK*192];
__device__ __nv_bfloat16 g_xm_bf[TTOK*192];
__device__ __nv_bfloat16 g_xout_bf[TTOK*384];
__device__ __nv_bfloat16 g_xn2_bf[TTOK*192];
__device__ __nv_bfloat16 g_hbuf[(size_t)8*TTOK*384];
// transposed bf16 weights [N][K]
__device__ __nv_bfloat16 g_wt_qs[576*192];
__device__ __nv_bfloat16 g_wt_qm[576*192];
__device__ __nv_bfloat16 g_wt_p [192*384];
__device__ __nv_bfloat16 g_wt_w1[8*384*192];
__device__ __nv_bfloat16 g_wt_w2[8*192*384];

// ---------------- helpers ------------------------------------------------
typedef unsigned long long ull;
__device__ __forceinline__ float warpsum_all(float v) {
    #pragma unroll
    for (int o = 16; o; o >>= 1) v += __shfl_xor_sync(0xffffffffu, v, o);
    return v;
}
__device__ __forceinline__ uint32_t smem_u32(const void* p) {
    uint32_t a;
    asm("{ .reg .u64 t; cvta.to.shared.u64 t, %1; cvt.u32.u64 %0, t; }" : "=r"(a) : "l"(p));
    return a;
}
__device__ __forceinline__ void ldsm_x4(uint32_t& r0, uint32_t& r1, uint32_t& r2,
                                        uint32_t& r3, uint32_t addr) {
    asm volatile("ldmatrix.sync.aligned.m8n8.x4.shared.b16 {%0,%1,%2,%3}, [%4];"
                 : "=r"(r0), "=r"(r1), "=r"(r2), "=r"(r3) : "r"(addr));
}
__device__ __forceinline__ void ldsm_x4_t(uint32_t& r0, uint32_t& r1, uint32_t& r2,
                                          uint32_t& r3, uint32_t addr) {
    asm volatile("ldmatrix.sync.aligned.m8n8.x4.trans.shared.b16 {%0,%1,%2,%3}, [%4];"
                 : "=r"(r0), "=r"(r1), "=r"(r2), "=r"(r3) : "r"(addr));
}
__device__ __forceinline__ void mma16816(float* c, uint32_t a0, uint32_t a1,
                                         uint32_t a2, uint32_t a3,
                                         uint32_t b0, uint32_t b1) {
    asm volatile("mma.sync.aligned.m16n8k16.row.col.f32.bf16.bf16.f32 "
        "{%0,%1,%2,%3}, {%4,%5,%6,%7}, {%8,%9}, {%0,%1,%2,%3};"
        : "+f"(c[0]), "+f"(c[1]), "+f"(c[2]), "+f"(c[3])
        : "r"(a0), "r"(a1), "r"(a2), "r"(a3), "r"(b0), "r"(b1));
}
__device__ __forceinline__ void cp16(uint32_t dst, const void* src, bool v) {
    asm volatile("cp.async.cg.shared.global [%0], [%1], 16, %2;"
                 :: "r"(dst), "l"(src), "r"(v ? 16u : 0u));
}
#define CP_COMMIT() asm volatile("cp.async.commit_group;")
#define CP_WAIT1()  asm volatile("cp.async.wait_group 1;")
#define CP_WAIT0()  asm volatile("cp.async.wait_group 0;")
#define SMEM_SWZ(o) ((o) ^ (((o) >> 3) & 0x70))
#define SMEM_SWZ64(o) ((o) ^ (((o) >> 3) & 0x30))

__device__ __forceinline__ uint32_t bf2(float x, float y) {
    __nv_bfloat162 t = __floats2bfloat162_rn(x, y);
    return *reinterpret_cast<uint32_t*>(&t);
}

// ---- 128x64 warp-tile MMA over one 64-K chunk (8 warps: 4m x 2n) ----------
__device__ __forceinline__ void mma_tile(uint32_t aB, uint32_t bB,
                                         float (&c)[2][4][4], int wm, int wn, int lane) {
    int g = lane >> 3, l7 = lane & 7;
    #pragma unroll
    for (int ks = 0; ks < 4; ks++) {
        uint32_t a[2][4];
        #pragma unroll
        for (int mi = 0; mi < 2; mi++) {
            int r = wm*32 + mi*16 + ((g & 1) << 3) + l7;
            int kb = ks*32 + ((g >> 1) << 4);
            ldsm_x4(a[mi][0], a[mi][1], a[mi][2], a[mi][3],
                    aB + SMEM_SWZ((uint32_t)(r*128 + kb)));
        }
        uint32_t b[4][2];
        #pragma unroll
        for (int np = 0; np < 2; np++) {
            int r = wn*32 + np*16 + ((g >> 1) << 3) + l7;
            int kb = ks*32 + ((g & 1) << 4);
            uint32_t r0, r1, r2, r3;
            ldsm_x4(r0, r1, r2, r3, bB + SMEM_SWZ((uint32_t)(r*128 + kb)));
            b[np*2][0] = r0;   b[np*2][1] = r1;
            b[np*2+1][0] = r2; b[np*2+1][1] = r3;
        }
        #pragma unroll
        for (int mi = 0; mi < 2; mi++)
            #pragma unroll
            for (int nj = 0; nj < 4; nj++)
                mma16816(c[mi][nj], a[mi][0], a[mi][1], a[mi][2], a[mi][3],
                         b[nj][0], b[nj][1]);
    }
}

// ---- 128x128 wide warp-tile MMA (8 warps: 4m x 2n, 64 n-cols per warp) -----
__device__ __forceinline__ void mma_tile_w(uint32_t aB, uint32_t bB,
                                           float (&c)[2][8][4], int wm, int wn, int lane) {
    int g = lane >> 3, l7 = lane & 7;
    #pragma unroll
    for (int ks = 0; ks < 4; ks++) {
        uint32_t a[2][4];
        #pragma unroll
        for (int mi = 0; mi < 2; mi++) {
            int r = wm*32 + mi*16 + ((g & 1) << 3) + l7;
            int kb = ks*32 + ((g >> 1) << 4);
            ldsm_x4(a[mi][0], a[mi][1], a[mi][2], a[mi][3],
                    aB + SMEM_SWZ((uint32_t)(r*128 + kb)));
        }
        uint32_t b[8][2];
        #pragma unroll
        for (int np = 0; np < 4; np++) {
            int r = wn*64 + np*16 + ((g >> 1) << 3) + l7;
            int kb = ks*32 + ((g & 1) << 4);
            uint32_t r0, r1, r2, r3;
            ldsm_x4(r0, r1, r2, r3, bB + SMEM_SWZ((uint32_t)(r*128 + kb)));
            b[np*2][0] = r0;   b[np*2][1] = r1;
            b[np*2+1][0] = r2; b[np*2+1][1] = r3;
        }
        #pragma unroll
        for (int mi = 0; mi < 2; mi++)
            #pragma unroll
            for (int nj = 0; nj < 8; nj++)
                mma16816(c[mi][nj], a[mi][0], a[mi][1], a[mi][2], a[mi][3],
                         b[nj][0], b[nj][1]);
    }
}

// ================= HMMA flash attention, register-resident P ================
// Block = (win, head), 256 threads / 8 warps; warp w owns S rows w*16..w*16+15.
// smem: sQ 16K | sK 16K | sV 8K (128x64B, SW64).
template<int MUT>
__global__ __launch_bounds__(256, 2) void attn_mma() {
    extern __shared__ uint8_t sm[];
    uint32_t base = (smem_u32(sm) + 1023u) & ~1023u;
    uint8_t* smp = sm + (base - smem_u32(sm));
    const uint32_t sQ = base, sK = base + 16384, sV = base + 32768;

    int tid = threadIdx.x, wid = tid >> 5, lane = tid & 31;
    int win = blockIdx.x >> 3, h = blockIdx.x & 7;
    const float* qkv = MUT ? g_qkv_m : g_qkv_s;
    const float SC = 0.20412414523193154f;   // 24^-0.5

    // mask-pattern selector: only last block in each dim is non-uniform
    int mw = win % 192;
    int sel = (((mw >> 6) == 2) ? 4 : 0) | ((((mw >> 3) & 7) == 7) ? 2 : 0)
            | (((mw & 7) == 7) ? 1 : 0);

    // ---------- staging ----------
    if (tid < 128) {
        int r = tid;
        int qrow = MUT ? ((r + 64) & 127) : r;
        const float4* qp = reinterpret_cast<const float4*>(
            qkv + (size_t)(win*128 + qrow)*576 + h*24);
        uint32_t w[12];
        #pragma unroll
        for (int i = 0; i < 6; i++) {
            float4 a = qp[i];
            w[2*i]   = bf2(a.x*SC, a.y*SC);
            w[2*i+1] = bf2(a.z*SC, a.w*SC);
        }
        *reinterpret_cast<uint4*>(smp + SMEM_SWZ((uint32_t)(r*128 + 0)))  = make_uint4(w[0],w[1],w[2],w[3]);
        *reinterpret_cast<uint4*>(smp + SMEM_SWZ((uint32_t)(r*128 + 16))) = make_uint4(w[4],w[5],w[6],w[7]);
        *reinterpret_cast<uint4*>(smp + SMEM_SWZ((uint32_t)(r*128 + 32))) = make_uint4(w[8],w[9],w[10],w[11]);
        *reinterpret_cast<uint4*>(smp + SMEM_SWZ((uint32_t)(r*128 + 48))) = make_uint4(0,0,0,0);
        // V natural rows: sV[key][dim], 64B rows (24 dims + 8 zero pad), SW64
        const float4* vp = reinterpret_cast<const float4*>(
            qkv + (size_t)(win*128 + r)*576 + h*24 + 384);
        uint32_t v[12];
        #pragma unroll
        for (int i = 0; i < 6; i++) {
            float4 a = vp[i];
            v[2*i]   = bf2(a.x, a.y);
            v[2*i+1] = bf2(a.z, a.w);
        }
        uint8_t* vb = smp + 32768;
        *reinterpret_cast<uint4*>(vb + SMEM_SWZ64((uint32_t)(r*64 + 0)))  = make_uint4(v[0],v[1],v[2],v[3]);
        *reinterpret_cast<uint4*>(vb + SMEM_SWZ64((uint32_t)(r*64 + 16))) = make_uint4(v[4],v[5],v[6],v[7]);
        *reinterpret_cast<uint4*>(vb + SMEM_SWZ64((uint32_t)(r*64 + 32))) = make_uint4(v[8],v[9],v[10],v[11]);
        *reinterpret_cast<uint4*>(vb + SMEM_SWZ64((uint32_t)(r*64 + 48))) = make_uint4(0,0,0,0);
    } else {
        int r = tid - 128;
        const float4* kp = reinterpret_cast<const float4*>(
            qkv + (size_t)(win*128 + r)*576 + h*24 + 192);
        uint32_t w[12];
        #pragma unroll
        for (int i = 0; i < 6; i++) {
            float4 a = kp[i];
            w[2*i]   = bf2(a.x, a.y);
            w[2*i+1] = bf2(a.z, a.w);
        }
        uint8_t* kbp = smp + 16384;
        *reinterpret_cast<uint4*>(kbp + SMEM_SWZ((uint32_t)(r*128 + 0)))  = make_uint4(w[0],w[1],w[2],w[3]);
        *reinterpret_cast<uint4*>(kbp + SMEM_SWZ((uint32_t)(r*128 + 16))) = make_uint4(w[4],w[5],w[6],w[7]);
        *reinterpret_cast<uint4*>(kbp + SMEM_SWZ((uint32_t)(r*128 + 32))) = make_uint4(w[8],w[9],w[10],w[11]);
        *reinterpret_cast<uint4*>(kbp + SMEM_SWZ((uint32_t)(r*128 + 48))) = make_uint4(0,0,0,0);
    }
    __syncthreads();

    int g = lane >> 3, l7 = lane & 7;
    int qr = lane >> 2, qc = (lane & 3) * 2;
    int r0 = wid * 16;

    // ---------- S = Q @ K^T : warp owns rows r0..r0+15, all 128 cols ----------
    float c[16][4] = {};
    #pragma unroll
    for (int ks = 0; ks < 2; ks++) {
        uint32_t a0, a1, a2, a3;
        int ar = r0 + ((g & 1) << 3) + l7;
        int akb = ks*32 + ((g >> 1) << 4);
        ldsm_x4(a0, a1, a2, a3, sQ + SMEM_SWZ((uint32_t)(ar*128 + akb)));
        #pragma unroll
        for (int np = 0; np < 8; np++) {
            int r = np*16 + ((g >> 1) << 3) + l7;
            int kb = ks*32 + ((g & 1) << 4);
            uint32_t b0, b1, b2, b3;
            ldsm_x4(b0, b1, b2, b3, sK + SMEM_SWZ((uint32_t)(r*128 + kb)));
            mma16816(c[2*np],   a0, a1, a2, a3, b0, b1);
            mma16816(c[2*np+1], a0, a1, a2, a3, b2, b3);
        }
    }

    // ---------- softmax in-register, pack P to A-fragments ----------
    const __nv_bfloat16* bm = g_bmh + ((size_t)(sel*8 + h))*16384;
    const __nv_bfloat16* mm = g_mmh + (size_t)sel*4096;
    int row0q = r0 + qr, row1q = r0 + 8 + qr;
    float sum0 = 0.f, sum1 = 0.f;
    uint32_t pa[8][4];
    #pragma unroll
    for (int nj = 0; nj < 16; nj++) {
        int col = nj*8 + qc;
        float bx0, by0, bx1, by1;
        if (MUT) {
            float2 m0 = __bfloat1622float2(*reinterpret_cast<const __nv_bfloat162*>(
                mm + (row0q & 63)*64 + (col & 63)));
            float2 m1 = __bfloat1622float2(*reinterpret_cast<const __nv_bfloat162*>(
                mm + (row1q & 63)*64 + (col & 63)));
            float g0 = ((row0q ^ col) & 64) ? -10000.f : 0.f;
            float g1 = ((row1q ^ col) & 64) ? -10000.f : 0.f;
            bx0 = m0.x + g0; by0 = m0.y + g0;
            bx1 = m1.x + g1; by1 = m1.y + g1;
        } else {
            float2 b0 = __bfloat1622float2(*reinterpret_cast<const __nv_bfloat162*>(
                bm + row0q*128 + col));
            float2 b1 = __bfloat1622float2(*reinterpret_cast<const __nv_bfloat162*>(
                bm + row1q*128 + col));
            bx0 = b0.x; by0 = b0.y;
            bx1 = b1.x; by1 = b1.y;
        }
        float p00 = __expf(c[nj][0] + bx0);
        float p01 = __expf(c[nj][1] + by0);
        float p10 = __expf(c[nj][2] + bx1);
        float p11 = __expf(c[nj][3] + by1);
        sum0 += p00 + p01;
        sum1 += p10 + p11;
        int kt = nj >> 1, half = (nj & 1) << 1;
        pa[kt][half + 0] = bf2(p00, p01);
        pa[kt][half + 1] = bf2(p10, p11);
    }
    sum0 += __shfl_xor_sync(0xffffffffu, sum0, 1);
    sum0 += __shfl_xor_sync(0xffffffffu, sum0, 2);
    sum1 += __shfl_xor_sync(0xffffffffu, sum1, 1);
    sum1 += __shfl_xor_sync(0xffffffffu, sum1, 2);

    // ---------- O = P @ V : A from registers, B via ldmatrix.trans on sV ----
    float o[3][4] = {};
    #pragma unroll
    for (int kt = 0; kt < 8; kt++) {
        int krow = kt*16 + ((g & 1) << 3) + l7;
        uint32_t b0, b1, b2, b3, d0, d1, d2, d3;
        ldsm_x4_t(b0, b1, b2, b3, sV + SMEM_SWZ64((uint32_t)(krow*64 + ((g >> 1) << 4))));
        ldsm_x4_t(d0, d1, d2, d3, sV + SMEM_SWZ64((uint32_t)(krow*64 + 32 + ((g >> 1) << 4))));
        mma16816(o[0], pa[kt][0], pa[kt][1], pa[kt][2], pa[kt][3], b0, b1);
        mma16816(o[1], pa[kt][0], pa[kt][1], pa[kt][2], pa[kt][3], b2, b3);
        mma16816(o[2], pa[kt][0], pa[kt][1], pa[kt][2], pa[kt][3], d0, d1);
    }

    // ---------- epilogue: divide by register row sums, store bf16 ----------
    int coff = MUT ? 0 : 192;
    float inv0 = 1.f / sum0, inv1 = 1.f / sum1;
    #pragma unroll
    for (int hh = 0; hh < 2; hh++) {
        int row = r0 + hh*8 + qr;
        float inv = hh ? inv1 : inv0;
        __nv_bfloat16* ob = g_xout_bf + (size_t)(win*128 + row)*384 + coff + h*24;
        #pragma unroll
        for (int nj = 0; nj < 3; nj++) {
            float v0 = o[nj][2*hh]   * inv;
            float v1 = o[nj][2*hh+1] * inv;
            *reinterpret_cast<uint32_t*>(ob + nj*8 + qc) = bf2(v0, v1);
        }
    }
}

// ---- shared mode-0 GEMM core: C fp32 = A @ Bt^T + bias ---------------------
__device__ __forceinline__ void gemm_core0(
        const __nv_bfloat16* __restrict__ A,
        const __nv_bfloat16* __restrict__ Bt,
        const float* __restrict__ bias,
        float* __restrict__ Cf, int K, int ldC, uint8_t* dyn_raw) {
    int tid = threadIdx.x, wid = tid >> 5, lane = tid & 31;
    int wm = wid >> 1, wn = wid & 1;
    int row0 = blockIdx.x * 128, col0 = blockIdx.y * 64;

    uint32_t aBase = (smem_u32(dyn_raw) + 1023u) & ~1023u;
    uint32_t bBase = aBase + 32768;

    int srow = tid >> 3, c16 = tid & 7;
    const __nv_bfloat16* arp[4]; uint32_t aOff[4];
    #pragma unroll
    for (int i = 0; i < 4; i++) {
        int r = i*32 + srow;
        aOff[i] = SMEM_SWZ((uint32_t)(r*128 + c16*16));
        arp[i] = A + (size_t)(row0 + r)*K + c16*8;
    }
    const __nv_bfloat16* brp[2]; uint32_t bOff[2];
    #pragma unroll
    for (int i = 0; i < 2; i++) {
        int r = i*32 + srow;
        bOff[i] = SMEM_SWZ((uint32_t)(r*128 + c16*16));
        brp[i] = Bt + (size_t)(col0 + r)*K + c16*8;
    }

    float c[2][4][4] = {};
    int nch = K >> 6;

    #pragma unroll
    for (int i = 0; i < 4; i++) cp16(aBase + aOff[i], arp[i], true);
    #pragma unroll
    for (int i = 0; i < 2; i++) cp16(bBase + bOff[i], brp[i], true);
    CP_COMMIT();

    for (int ic = 0; ic < nch; ic++) {
        if (ic + 1 < nch) {
            int buf = (ic + 1) & 1, kc = (ic + 1) << 6;
            #pragma unroll
            for (int i = 0; i < 4; i++)
                cp16(aBase + buf*16384 + aOff[i], arp[i] + kc, true);
            #pragma unroll
            for (int i = 0; i < 2; i++)
                cp16(bBase + buf*8192 + bOff[i], brp[i] + kc, true);
            CP_COMMIT();
            CP_WAIT1();
        } else {
            CP_WAIT0();
        }
        __syncthreads();
        mma_tile(aBase + (ic & 1)*16384, bBase + (ic & 1)*8192, c, wm, wn, lane);
        __syncthreads();
    }

    int qr = lane >> 2, qc = (lane & 3) * 2;
    #pragma unroll
    for (int mi = 0; mi < 2; mi++) {
        #pragma unroll
        for (int h = 0; h < 2; h++) {
            int lr = wm*32 + mi*16 + h*8 + qr;
            #pragma unroll
            for (int nj = 0; nj < 4; nj++) {
                int col = col0 + wn*32 + nj*8 + qc;
                size_t crow = (size_t)(row0 + lr)*ldC + col;
                *reinterpret_cast<float2*>(Cf + crow) =
                    make_float2(c[mi][nj][2*h] + bias[col],
                                c[mi][nj][2*h+1] + bias[col+1]);
            }
        }
    }
}

// ---- merged QKV GEMM: z=0 self, z=1 mutual ----------------------------------
__global__ __launch_bounds__(256, 3) void gemm_qkv(const float* __restrict__ qsb,
                                                   const float* __restrict__ qmb) {
    extern __shared__ uint8_t dyn_raw[];
    if (blockIdx.z == 0)
        gemm_core0(g_xw_bf, g_wt_qs, qsb, g_qkv_s, 192, 576, dyn_raw);
    else
        gemm_core0(g_xm_bf, g_wt_qm, qmb, g_qkv_m, 192, 576, dyn_raw);
}

// ---- proj GEMM ---------------------------------------------------------------
__global__ __launch_bounds__(256, 3) void gemm_proj(
        const __nv_bfloat16* __restrict__ A, const __nv_bfloat16* __restrict__ Bt,
        const float* __restrict__ bias, float* __restrict__ Cf, int K, int ldC) {
    extern __shared__ uint8_t dyn_raw[];
    gemm_core0(A, Bt, bias, Cf, K, ldC, dyn_raw);
}

// ======= MoE FC1: gather + gelu -> g_hbuf, wide 128x128 tile, K=192 =========
__global__ __launch_bounds__(256) void gemm_moe1(const float* __restrict__ b1) {
    extern __shared__ uint8_t dyn_raw[];
    __shared__ int s_tok[128];
    int tid = threadIdx.x, wid = tid >> 5, lane = tid & 31;
    int wm = wid >> 1, wn = wid & 1;
    int row0 = blockIdx.x * 128, col0 = blockIdx.y * 128;
    int e = blockIdx.z;
    int cnt = g_cnt[e];
    if (row0 >= cnt) return;
    const __nv_bfloat16* W1te = g_wt_w1 + (size_t)e*73728;
    const float* b1e = b1 + e*384;

    if (tid < 128) {
        int slot = row0 + tid;
        s_tok[tid] = (slot < cnt) ? g_gidx[e*TTOK + slot] : -1;
    }
    __syncthreads();

    uint32_t aBase = (smem_u32(dyn_raw) + 1023u) & ~1023u;
    uint32_t bBase = aBase + 32768;

    int srow = tid >> 3, c16 = tid & 7;
    const __nv_bfloat16* arp[4]; bool av[4]; uint32_t off[4];
    const __nv_bfloat16* brp[4];
    #pragma unroll
    for (int i = 0; i < 4; i++) {
        int r = i*32 + srow;
        off[i] = SMEM_SWZ((uint32_t)(r*128 + c16*16));
        int tk = s_tok[r];
        av[i] = (tk >= 0);
        arp[i] = g_xn2_bf + (size_t)(av[i] ? tk : 0)*192 + c16*8;
        brp[i] = W1te + (size_t)(col0 + r)*192 + c16*8;
    }

    float c[2][8][4] = {};

    #pragma unroll
    for (int i = 0; i < 4; i++) cp16(aBase + off[i], arp[i], av[i]);
    #pragma unroll
    for (int i = 0; i < 4; i++) cp16(bBase + off[i], brp[i], true);
    CP_COMMIT();

    for (int ic = 0; ic < 3; ic++) {
        if (ic + 1 < 3) {
            int buf = (ic + 1) & 1, kc = (ic + 1) << 6;
            #pragma unroll
            for (int i = 0; i < 4; i++)
                cp16(aBase + buf*16384 + off[i], arp[i] + kc, av[i]);
            #pragma unroll
            for (int i = 0; i < 4; i++)
                cp16(bBase + buf*16384 + off[i], brp[i] + kc, true);
            CP_COMMIT();
            CP_WAIT1();
        } else {
            CP_WAIT0();
        }
        __syncthreads();
        mma_tile_w(aBase + (ic & 1)*16384, bBase + (ic & 1)*16384, c, wm, wn, lane);
        __syncthreads();
    }

    int qr = lane >> 2, qc = (lane & 3) * 2;
    #pragma unroll
    for (int mi = 0; mi < 2; mi++) {
        #pragma unroll
        for (int h = 0; h < 2; h++) {
            int lr = wm*32 + mi*16 + h*8 + qr;
            if (s_tok[lr] >= 0) {
                size_t hrow = ((size_t)e*TTOK + row0 + lr)*384;
                #pragma unroll
                for (int nj = 0; nj < 8; nj++) {
                    int col = col0 + wn*64 + nj*8 + qc;
                    float h0 = c[mi][nj][2*h]   + b1e[col];
                    float h1 = c[mi][nj][2*h+1] + b1e[col+1];
                    h0 = h0 * normcdff(h0);
                    h1 = h1 * normcdff(h1);
                    *reinterpret_cast<uint32_t*>(g_hbuf + hrow + col) = bf2(h0, h1);
                }
            }
        }
    }
}

// ======= MoE FC2: weighted scatter -> contrib buffers, K=384 ================
__global__ __launch_bounds__(256, 3) void gemm_moe2(const float* __restrict__ b2) {
    extern __shared__ uint8_t dyn_raw[];
    __shared__ int s_tok[128]; __shared__ float s_wgt[128]; __shared__ int s_rnk[128];

    int tid = threadIdx.x, wid = tid >> 5, lane = tid & 31;
    int wm = wid >> 1, wn = wid & 1;
    int row0 = blockIdx.x * 128, col0 = blockIdx.y * 64;
    int e = blockIdx.z;
    int cnt = g_cnt[e];
    if (row0 >= cnt) return;
    const __nv_bfloat16* Bte = g_wt_w2 + (size_t)e*73728;
    const float* be = b2 + e*192;
    const __nv_bfloat16* Ae = g_hbuf + (size_t)e*TTOK*384;

    if (tid < 128) {
        int slot = row0 + tid;
        if (slot < cnt) {
            s_tok[tid] = g_gidx[e*TTOK + slot];
            s_wgt[tid] = g_gw[e*TTOK + slot];
            s_rnk[tid] = g_grank[e*TTOK + slot];
        } else s_tok[tid] = -1;
    }
    __syncthreads();

    uint32_t aBase = (smem_u32(dyn_raw) + 1023u) & ~1023u;
    uint32_t bBase = aBase + 32768;

    int srow = tid >> 3, c16 = tid & 7;
    const __nv_bfloat16* arp[4]; bool av[4]; uint32_t aOff[4];
    #pragma unroll
    for (int i = 0; i < 4; i++) {
        int r = i*32 + srow;
        aOff[i] = SMEM_SWZ((uint32_t)(r*128 + c16*16));
        av[i] = (row0 + r < cnt);
        arp[i] = Ae + (size_t)(av[i] ? (row0 + r) : 0)*384 + c16*8;
    }
    const __nv_bfloat16* brp[2]; uint32_t bOff[2];
    #pragma unroll
    for (int i = 0; i < 2; i++) {
        int r = i*32 + srow;
        bOff[i] = SMEM_SWZ((uint32_t)(r*128 + c16*16));
        brp[i] = Bte + (size_t)(col0 + r)*384 + c16*8;
    }

    float c[2][4][4] = {};

    #pragma unroll
    for (int i = 0; i < 4; i++) cp16(aBase + aOff[i], arp[i], av[i]);
    #pragma unroll
    for (int i = 0; i < 2; i++) cp16(bBase + bOff[i], brp[i], true);
    CP_COMMIT();

    for (int ic = 0; ic < 6; ic++) {
        if (ic + 1 < 6) {
            int buf = (ic + 1) & 1, kc = (ic + 1) << 6;
            #pragma unroll
            for (int i = 0; i < 4; i++)
                cp16(aBase + buf*16384 + aOff[i], arp[i] + kc, av[i]);
            #pragma unroll
            for (int i = 0; i < 2; i++)
                cp16(bBase + buf*8192 + bOff[i], brp[i] + kc, true);
            CP_COMMIT();
            CP_WAIT1();
        } else {
            CP_WAIT0();
        }
        __syncthreads();
        mma_tile(aBase + (ic & 1)*16384, bBase + (ic & 1)*8192, c, wm, wn, lane);
        __syncthreads();
    }

    int qr = lane >> 2, qc = (lane & 3) * 2;
    #pragma unroll
    for (int mi = 0; mi < 2; mi++) {
        #pragma unroll
        for (int h = 0; h < 2; h++) {
            int lr = wm*32 + mi*16 + h*8 + qr;
            int tk = s_tok[lr];
            if (tk >= 0) {
                float w = s_wgt[lr];
                float* dst = (s_rnk[lr] == 0) ? g_contrib0 : g_contrib1;
                #pragma unroll
                for (int nj = 0; nj < 4; nj++) {
                    int col = col0 + wn*32 + nj*8 + qc;
                    *reinterpret_cast<float2*>(dst + (size_t)tk*192 + col) =
                        make_float2(w*(c[mi][nj][2*h]   + be[col]),
                                    w*(c[mi][nj][2*h+1] + be[col+1]));
                }
            }
        }
    }
}

// ---- merged prep: transpose (0-359) | bmh (360-423) | mmh (424-431) | pos (432)
__global__ __launch_bounds__(256) void k_prep_all(
        const float* __restrict__ qs, const float* __restrict__ qm,
        const float* __restrict__ pw, const float* __restrict__ W1,
        const float* __restrict__ W2, const float* __restrict__ rpb,
        const float* __restrict__ mask) {
    __shared__ float tile[64][65];
    int bid = blockIdx.x;
    if (bid < 360) {
        const float* src; __nv_bfloat16* dst; int K, N, tk, tn;
        if (bid < 27)       { src = qs; dst = g_wt_qs; K = 192; N = 576; tk = bid/9; tn = bid%9; }
        else if (bid < 54)  { int j = bid-27; src = qm; dst = g_wt_qm; K = 192; N = 576; tk = j/9; tn = j%9; }
        else if (bid < 72)  { int j = bid-54; src = pw; dst = g_wt_p;  K = 384; N = 192; tk = j/3; tn = j%3; }
        else if (bid < 216) { int j = bid-72;  int e = j/18; j %= 18;
                              src = W1 + (size_t)e*73728; dst = g_wt_w1 + (size_t)e*73728;
                              K = 192; N = 384; tk = j/6; tn = j%6; }
        else                { int j = bid-216; int e = j/18; j %= 18;
                              src = W2 + (size_t)e*73728; dst = g_wt_w2 + (size_t)e*73728;
                              K = 384; N = 192; tk = j/3; tn = j%3; }
        int rr = threadIdx.x >> 6, cc = threadIdx.x & 63;
        #pragma unroll 4
        for (int i = 0; i < 16; i++) {
            int r = rr + 4*i;
            tile[r][cc] = src[(size_t)(tk*64 + r)*N + tn*64 + cc];
        }
        __syncthreads();
        #pragma unroll 4
        for (int i = 0; i < 16; i++) {
            int r = rr + 4*i;
            dst[(size_t)(tn*64 + r)*K + tk*64 + cc] = __float2bfloat16_rn(tile[cc][r]);
        }
    } else if (bid < 424) {
        // combined mask+bias bf16 table: one block per (sel, h); 8 distinct masks
        int idx = bid - 360;
        int sel = idx >> 3, h = idx & 7;
        int mwr = ((sel & 4) ? 2 : 0)*64 + ((sel & 2) ? 7 : 0)*8 + ((sel & 1) ? 7 : 0);
        const float* mrow = mask + (size_t)mwr*16384;
        __nv_bfloat16* dst = g_bmh + (size_t)idx*16384;
        for (int e = threadIdx.x; e < 8192; e += 256) {
            int q = e >> 6, k2 = (e & 63)*2;
            int dn = q >> 6, hn = (q >> 3) & 7, wn = q & 7;
            float v[2];
            #pragma unroll
            for (int j = 0; j < 2; j++) {
                int k = k2 + j;
                int dm = k >> 6, hm = (k >> 3) & 7, wm = k & 7;
                int rp = (dn - dm + 1)*225 + (hn - hm + 7)*15 + (wn - wm + 7);
                v[j] = mrow[q*128 + k] + rpb[rp*8 + h];
            }
            *reinterpret_cast<uint32_t*>(dst + q*128 + k2) = bf2(v[0], v[1]);
        }
    } else if (bid < 432) {
        // mask quadrant bf16: one block per sel
        int sel = bid - 424;
        int mwr = ((sel & 4) ? 2 : 0)*64 + ((sel & 2) ? 7 : 0)*8 + ((sel & 1) ? 7 : 0);
        const float* mrow = mask + (size_t)mwr*16384;
        __nv_bfloat16* dst = g_mmh + (size_t)sel*4096;
        for (int e = threadIdx.x; e < 2048; e += 256) {
            int q = e >> 5, k2 = (e & 31)*2;
            float v0 = mrow[q*128 + k2], v1 = mrow[q*128 + k2 + 1];
            *reinterpret_cast<uint32_t*>(dst + q*64 + k2) = bf2(v0, v1);
        }
    } else {
        int c = threadIdx.x;
        if (c >= 192) return;
        if (c < 8) g_cnt[c] = 0;
        const float TWO_PI = 6.283185307179586f;
        const float denom = 8.0f + 1e-6f;
        int f = (c < 96) ? c : c - 96;
        float expo = (float)(f & ~1) / 96.0f;
        float dt = powf(10000.0f, expo);
        for (int n = 0; n < 64; n++) {
            int i = n >> 3, j = n & 7;
            float base = (c < 96) ? (float)(i + 1) : (float)(j + 1);
            float v = base / denom * TWO_PI / dt;
            g_pos[n*192 + c] = (f & 1) ? cosf(v) : sinf(v);
        }
    }
}

// ---------------- LN1 + roll + window partition -> bf16 (warp per token) -----
__global__ __launch_bounds__(256) void ln_partition(const float* __restrict__ x,
                             const float* __restrict__ w1,
                             const float* __restrict__ b1) {
    int t = (blockIdx.x*blockDim.x + threadIdx.x) >> 5;
    int lane = threadIdx.x & 31;
    int win = t >> 7, n = t & 127;
    int b_  = win / 192; int rem = win % 192;
    int dd  = rem / 64;  int rem2 = rem % 64;
    int hh  = rem2 >> 3; int ww = rem2 & 7;
    int wd  = n >> 6, wh = (n >> 3) & 7, wwp = n & 7;
    int ds = dd*2 + wd, hs = hh*8 + wh, ws = ww*8 + wwp;
    int d = ds + 1; if (d >= 6) d -= 6;
    int h = (hs + 4) & 63;
    int w = (ws + 4) & 63;
    const float* xr = x + (size_t)(((b_*6 + d)*64 + h)*64 + w)*192;
    float v[6];
    float s1 = 0.f, s2 = 0.f;
    #pragma unroll
    for (int k = 0; k < 6; k++) {
        v[k] = xr[lane + 32*k];
        s1 += v[k]; s2 += v[k]*v[k];
    }
    s1 = warpsum_all(s1); s2 = warpsum_all(s2);
    float mu  = s1 * (1.f/192.f);
    float var = s2 * (1.f/192.f) - mu*mu;
    float rstd = rsqrtf(var + 1e-5f);
    const float* pr = g_pos + (n & 63)*192;
    #pragma unroll
    for (int k = 0; k < 6; k++) {
        int cc = lane + 32*k;
        float y = (v[k] - mu) * rstd * w1[cc] + b1[cc];
        g_xw_bf[(size_t)t*192 + cc] = __float2bfloat16_rn(y);
        g_xm_bf[(size_t)t*192 + cc] = __float2bfloat16_rn(y + pr[cc]);
    }
}

// --------- residual (writes out directly) + LN2 + gate top-2 -----------------
__global__ __launch_bounds__(256) void resid_gate(const float* __restrict__ x,
                           const float* __restrict__ n2w, const float* __restrict__ n2b,
                           const float* __restrict__ gw,  const float* __restrict__ gb,
                           float* __restrict__ out) {
    __shared__ float s_gw[8*192];
    for (int i = threadIdx.x; i < 1536; i += 256) {
        int j = i / 192, cc = i % 192;
        s_gw[i] = gw[cc*8 + j];
    }
    __syncthreads();
    int t = (blockIdx.x*blockDim.x + threadIdx.x) >> 5;
    int lane = threadIdx.x & 31;
    int b_ = t / 24576; int rrem = t % 24576;
    int d  = rrem / 4096; int r2 = rrem % 4096;
    int hh_ = r2 / 64; int ww_ = r2 % 64;
    int ds = d - 1; if (ds < 0) ds += 6;
    int hs = (hh_ + 60) & 63;
    int ws = (ww_ + 60) & 63;
    int dd = ds >> 1, wd = ds & 1;
    int hblk = hs >> 3, wh = hs & 7;
    int wblk = ws >> 3, wwp = ws & 7;
    int win = ((b_*3 + dd)*8 + hblk)*8 + wblk;
    int n = wd*64 + wh*8 + wwp;
    const float* ar = g_attnbuf + (size_t)(win*128 + n)*192;
    const float* xr = x + (size_t)t*192;
    float v[6];
    float s1 = 0.f, s2 = 0.f;
    #pragma unroll
    for (int k = 0; k < 6; k++) {
        int cc = lane + 32*k;
        v[k] = xr[cc] + ar[cc];
        out[(size_t)t*192 + cc] = v[k];
        s1 += v[k]; s2 += v[k]*v[k];
    }
    s1 = warpsum_all(s1); s2 = warpsum_all(s2);
    float mu  = s1 * (1.f/192.f);
    float var = s2 * (1.f/192.f) - mu*mu;
    float rstd = rsqrtf(var + 1e-5f);
    float g[8] = {};
    #pragma unroll
    for (int k = 0; k < 6; k++) {
        int cc = lane + 32*k;
        float xn = (v[k] - mu) * rstd * n2w[cc] + n2b[cc];
        g_xn2_bf[(size_t)t*192 + cc] = __float2bfloat16_rn(xn);
        #pragma unroll
        for (int j = 0; j < 8; j++) g[j] = fmaf(xn, s_gw[j*192 + cc], g[j]);
    }
    #pragma unroll
    for (int j = 0; j < 8; j++) g[j] = warpsum_all(g[j]);
    if (lane == 0) {
        float L[8];
        #pragma unroll
        for (int j = 0; j < 8; j++) L[j] = g[j] + gb[j];
        int e0 = 0;
        #pragma unroll
        for (int j = 1; j < 8; j++) if (L[j] > L[e0]) e0 = j;
        int e1 = (e0 == 0) ? 1 : 0;
        #pragma unroll
        for (int j = 0; j < 8; j++) if (j != e0 && L[j] > L[e1]) e1 = j;
        float w0 = 1.f / (1.f + __expf(L[e1] - L[e0]));
        float w1 = 1.f - w0;
        int p0 = atomicAdd(&g_cnt[e0], 1);
        g_gidx[e0*TTOK + p0] = t; g_gw[e0*TTOK + p0] = w0; g_grank[e0*TTOK + p0] = 0;
        int p1 = atomicAdd(&g_cnt[e1], 1);
        g_gidx[e1*TTOK + p1] = t; g_gw[e1*TTOK + p1] = w1; g_grank[e1*TTOK + p1] = 1;
    }
}

// ---------------- finalize: out += contrib0 + contrib1 -----------------------
__global__ void finalize(float* __restrict__ out) {
    int i = blockIdx.x*blockDim.x + threadIdx.x;
    if (i < TTOK*48) {
        float4 a  = reinterpret_cast<const float4*>(out)[i];
        float4 c0 = reinterpret_cast<const float4*>(g_contrib0)[i];
        float4 c1 = reinterpret_cast<const float4*>(g_contrib1)[i];
        reinterpret_cast<float4*>(out)[i] =
            make_float4(a.x + c0.x + c1.x, a.y + c0.y + c1.y,
                        a.z + c0.z + c1.z, a.w + c0.w + c1.w);
    }
}

// ---------------- host launcher -----------------------------------------------
extern "C" void kernel_launch(void* const* d_in, const int* in_sizes, int n_in,
                              void* d_out, int out_size) {
    const float* x    = (const float*)d_in[0];
    const float* mask = (const float*)d_in[1];
    const float* n1w  = (const float*)d_in[2];
    const float* n1b  = (const float*)d_in[3];
    const float* qsw  = (const float*)d_in[4];
    const float* qsb  = (const float*)d_in[5];
    const float* qmw  = (const float*)d_in[6];
    const float* qmb  = (const float*)d_in[7];
    const float* rpb  = (const float*)d_in[8];
    const float* pw   = (const float*)d_in[9];
    const float* pb   = (const float*)d_in[10];
    const float* n2w  = (const float*)d_in[11];
    const float* n2b  = (const float*)d_in[12];
    const float* gw   = (const float*)d_in[13];
    const float* gb   = (const float*)d_in[14];
    const float* W1   = (const float*)d_in[15];
    const float* b1   = (const float*)d_in[16];
    const float* W2   = (const float*)d_in[17];
    const float* b2   = (const float*)d_in[18];
    float* out = (float*)d_out;

    const int DSMEM  = 50176;   // 48KB + align pad
    const int DSMEM1 = 66560;   // 64KB + align pad (wide FC1)
    const int ASMEM  = 41984;   // attn: 40KB tiles + align pad
    cudaFuncSetAttribute(gemm_qkv,    cudaFuncAttributeMaxDynamicSharedMemorySize, DSMEM);
    cudaFuncSetAttribute(gemm_proj,   cudaFuncAttributeMaxDynamicSharedMemorySize, DSMEM);
    cudaFuncSetAttribute(gemm_moe1,   cudaFuncAttributeMaxDynamicSharedMemorySize, DSMEM1);
    cudaFuncSetAttribute(gemm_moe2,   cudaFuncAttributeMaxDynamicSharedMemorySize, DSMEM);
    cudaFuncSetAttribute(attn_mma<0>, cudaFuncAttributeMaxDynamicSharedMemorySize, ASMEM);
    cudaFuncSetAttribute(attn_mma<1>, cudaFuncAttributeMaxDynamicSharedMemorySize, ASMEM);

    void *p_xout, *p_attn, *p_wp;
    cudaGetSymbolAddress(&p_xout, g_xout_bf);
    cudaGetSymbolAddress(&p_attn, g_attnbuf);
    cudaGetSymbolAddress(&p_wp,   g_wt_p);

    k_prep_all<<<433, 256>>>(qsw, qmw, pw, W1, W2, rpb, mask);
    ln_partition<<<6144, 256>>>(x, n1w, n1b);
    gemm_qkv<<<dim3(384, 9, 2), 256, DSMEM>>>(qsb, qmb);
    attn_mma<0><<<3072, 256, ASMEM>>>();                   // <- profiled slot
    attn_mma<1><<<3072, 256, ASMEM>>>();
    gemm_proj<<<dim3(384, 3), 256, DSMEM>>>((const __nv_bfloat16*)p_xout,
        (const __nv_bfloat16*)p_wp, pb, (float*)p_attn, 384, 192);
    resid_gate<<<6144, 256>>>(x, n2w, n2b, gw, gb, out);
    gemm_moe1<<<dim3(384, 3, 8), 256, DSMEM1>>>(b1);
    gemm_moe2<<<dim3(384, 3, 8), 256, DSMEM>>>(b2);
    finalize<<<9216, 256>>>(out);
}

// round 17
// speedup vs baseline: 1.0669x; 1.0259x over previous
#include <cuda_runtime.h>
#include <cuda_bf16.h>
#include <math.h>
#include <cstdint>

#define TTOK 49152      // total tokens = 2*6*64*64
#define NWIN 384

// ---------------- scratch (device globals; no allocations allowed) ----------
__device__ float g_qkv_s[TTOK*576];     // qkv fp32 (self)
__device__ float g_qkv_m[TTOK*576];     // qkv fp32 (mutual)
__device__ float g_attnbuf[TTOK*192];   // proj output (window order)
__device__ float g_pos[64*192];
__device__ __nv_bfloat16 g_bmh[8*8*128*128]; // combined mask+bias bf16 [sel][h][q][k]
__device__ __nv_bfloat16 g_mmh[8*64*64];     // mask quadrant bf16 [sel][q][k]
__device__ int   g_cnt[8];
__device__ int   g_gidx[8*TTOK];
__device__ float g_gw[8*TTOK];
__device__ int   g_grank[8*TTOK];
__device__ float g_contrib0[TTOK*192];
__device__ float g_contrib1[TTOK*192];
// bf16 activation buffers for tensor-core GEMMs
__device__ __nv_bfloat16 g_xw_bf[TTOK*192];
__device__ __nv_bfloat16 g_xm_bf[TTOK*192];
__device__ __nv_bfloat16 g_xout_bf[TTOK*384];
__device__ __nv_bfloat16 g_xn2_bf[TTOK*192];
__device__ __nv_bfloat16 g_hbuf[(size_t)8*TTOK*384];
// transposed bf16 weights [N][K]
__device__ __nv_bfloat16 g_wt_qs[576*192];
__device__ __nv_bfloat16 g_wt_qm[576*192];
__device__ __nv_bfloat16 g_wt_p [192*384];
__device__ __nv_bfloat16 g_wt_w1[8*384*192];
__device__ __nv_bfloat16 g_wt_w2[8*192*384];

// ---------------- helpers ------------------------------------------------
typedef unsigned long long ull;
__device__ __forceinline__ float warpsum_all(float v) {
    #pragma unroll
    for (int o = 16; o; o >>= 1) v += __shfl_xor_sync(0xffffffffu, v, o);
    return v;
}
__device__ __forceinline__ uint32_t smem_u32(const void* p) {
    uint32_t a;
    asm("{ .reg .u64 t; cvta.to.shared.u64 t, %1; cvt.u32.u64 %0, t; }" : "=r"(a) : "l"(p));
    return a;
}
__device__ __forceinline__ void ldsm_x4(uint32_t& r0, uint32_t& r1, uint32_t& r2,
                                        uint32_t& r3, uint32_t addr) {
    asm volatile("ldmatrix.sync.aligned.m8n8.x4.shared.b16 {%0,%1,%2,%3}, [%4];"
                 : "=r"(r0), "=r"(r1), "=r"(r2), "=r"(r3) : "r"(addr));
}
__device__ __forceinline__ void ldsm_x4_t(uint32_t& r0, uint32_t& r1, uint32_t& r2,
                                          uint32_t& r3, uint32_t addr) {
    asm volatile("ldmatrix.sync.aligned.m8n8.x4.trans.shared.b16 {%0,%1,%2,%3}, [%4];"
                 : "=r"(r0), "=r"(r1), "=r"(r2), "=r"(r3) : "r"(addr));
}
__device__ __forceinline__ void mma16816(float* c, uint32_t a0, uint32_t a1,
                                         uint32_t a2, uint32_t a3,
                                         uint32_t b0, uint32_t b1) {
    asm volatile("mma.sync.aligned.m16n8k16.row.col.f32.bf16.bf16.f32 "
        "{%0,%1,%2,%3}, {%4,%5,%6,%7}, {%8,%9}, {%0,%1,%2,%3};"
        : "+f"(c[0]), "+f"(c[1]), "+f"(c[2]), "+f"(c[3])
        : "r"(a0), "r"(a1), "r"(a2), "r"(a3), "r"(b0), "r"(b1));
}
__device__ __forceinline__ void cp16(uint32_t dst, const void* src, bool v) {
    asm volatile("cp.async.cg.shared.global [%0], [%1], 16, %2;"
                 :: "r"(dst), "l"(src), "r"(v ? 16u : 0u));
}
#define CP_COMMIT() asm volatile("cp.async.commit_group;")
#define CP_WAIT1()  asm volatile("cp.async.wait_group 1;")
#define CP_WAIT0()  asm volatile("cp.async.wait_group 0;")
#define SMEM_SWZ(o) ((o) ^ (((o) >> 3) & 0x70))
#define SMEM_SWZ64(o) ((o) ^ (((o) >> 3) & 0x30))

__device__ __forceinline__ uint32_t bf2(float x, float y) {
    __nv_bfloat162 t = __floats2bfloat162_rn(x, y);
    return *reinterpret_cast<uint32_t*>(&t);
}

// ---- 128x64 warp-tile MMA over one 64-K chunk (8 warps: 4m x 2n) ----------
__device__ __forceinline__ void mma_tile(uint32_t aB, uint32_t bB,
                                         float (&c)[2][4][4], int wm, int wn, int lane) {
    int g = lane >> 3, l7 = lane & 7;
    #pragma unroll
    for (int ks = 0; ks < 4; ks++) {
        uint32_t a[2][4];
        #pragma unroll
        for (int mi = 0; mi < 2; mi++) {
            int r = wm*32 + mi*16 + ((g & 1) << 3) + l7;
            int kb = ks*32 + ((g >> 1) << 4);
            ldsm_x4(a[mi][0], a[mi][1], a[mi][2], a[mi][3],
                    aB + SMEM_SWZ((uint32_t)(r*128 + kb)));
        }
        uint32_t b[4][2];
        #pragma unroll
        for (int np = 0; np < 2; np++) {
            int r = wn*32 + np*16 + ((g >> 1) << 3) + l7;
            int kb = ks*32 + ((g & 1) << 4);
            uint32_t r0, r1, r2, r3;
            ldsm_x4(r0, r1, r2, r3, bB + SMEM_SWZ((uint32_t)(r*128 + kb)));
            b[np*2][0] = r0;   b[np*2][1] = r1;
            b[np*2+1][0] = r2; b[np*2+1][1] = r3;
        }
        #pragma unroll
        for (int mi = 0; mi < 2; mi++)
            #pragma unroll
            for (int nj = 0; nj < 4; nj++)
                mma16816(c[mi][nj], a[mi][0], a[mi][1], a[mi][2], a[mi][3],
                         b[nj][0], b[nj][1]);
    }
}

// ---- 128x128 wide warp-tile MMA (8 warps: 4m x 2n, 64 n-cols per warp) -----
__device__ __forceinline__ void mma_tile_w(uint32_t aB, uint32_t bB,
                                           float (&c)[2][8][4], int wm, int wn, int lane) {
    int g = lane >> 3, l7 = lane & 7;
    #pragma unroll
    for (int ks = 0; ks < 4; ks++) {
        uint32_t a[2][4];
        #pragma unroll
        for (int mi = 0; mi < 2; mi++) {
            int r = wm*32 + mi*16 + ((g & 1) << 3) + l7;
            int kb = ks*32 + ((g >> 1) << 4);
            ldsm_x4(a[mi][0], a[mi][1], a[mi][2], a[mi][3],
                    aB + SMEM_SWZ((uint32_t)(r*128 + kb)));
        }
        uint32_t b[8][2];
        #pragma unroll
        for (int np = 0; np < 4; np++) {
            int r = wn*64 + np*16 + ((g >> 1) << 3) + l7;
            int kb = ks*32 + ((g & 1) << 4);
            uint32_t r0, r1, r2, r3;
            ldsm_x4(r0, r1, r2, r3, bB + SMEM_SWZ((uint32_t)(r*128 + kb)));
            b[np*2][0] = r0;   b[np*2][1] = r1;
            b[np*2+1][0] = r2; b[np*2+1][1] = r3;
        }
        #pragma unroll
        for (int mi = 0; mi < 2; mi++)
            #pragma unroll
            for (int nj = 0; nj < 8; nj++)
                mma16816(c[mi][nj], a[mi][0], a[mi][1], a[mi][2], a[mi][3],
                         b[nj][0], b[nj][1]);
    }
}

// ================= HMMA flash attention, register-resident P ================
// Block = (win, head), 256 threads / 8 warps; warp w owns S rows w*16..w*16+15.
// MUT: S is block-diagonal -> compute only the warp's 64-col half (removed
// terms are exact fp32 zeros: expf(s - 1e4) underflows).
// smem: sQ 16K | sK 16K | sV 8K (128x64B, SW64).
template<int MUT>
__global__ __launch_bounds__(256, 2) void attn_mma() {
    extern __shared__ uint8_t sm[];
    uint32_t base = (smem_u32(sm) + 1023u) & ~1023u;
    uint8_t* smp = sm + (base - smem_u32(sm));
    const uint32_t sQ = base, sK = base + 16384, sV = base + 32768;

    int tid = threadIdx.x, wid = tid >> 5, lane = tid & 31;
    int win = blockIdx.x >> 3, h = blockIdx.x & 7;
    const float* qkv = MUT ? g_qkv_m : g_qkv_s;
    const float SC = 0.20412414523193154f;   // 24^-0.5

    // mask-pattern selector: only last block in each dim is non-uniform
    int mw = win % 192;
    int sel = (((mw >> 6) == 2) ? 4 : 0) | ((((mw >> 3) & 7) == 7) ? 2 : 0)
            | (((mw & 7) == 7) ? 1 : 0);

    // ---------- staging ----------
    if (tid < 128) {
        int r = tid;
        int qrow = MUT ? ((r + 64) & 127) : r;
        const float4* qp = reinterpret_cast<const float4*>(
            qkv + (size_t)(win*128 + qrow)*576 + h*24);
        uint32_t w[12];
        #pragma unroll
        for (int i = 0; i < 6; i++) {
            float4 a = qp[i];
            w[2*i]   = bf2(a.x*SC, a.y*SC);
            w[2*i+1] = bf2(a.z*SC, a.w*SC);
        }
        *reinterpret_cast<uint4*>(smp + SMEM_SWZ((uint32_t)(r*128 + 0)))  = make_uint4(w[0],w[1],w[2],w[3]);
        *reinterpret_cast<uint4*>(smp + SMEM_SWZ((uint32_t)(r*128 + 16))) = make_uint4(w[4],w[5],w[6],w[7]);
        *reinterpret_cast<uint4*>(smp + SMEM_SWZ((uint32_t)(r*128 + 32))) = make_uint4(w[8],w[9],w[10],w[11]);
        *reinterpret_cast<uint4*>(smp + SMEM_SWZ((uint32_t)(r*128 + 48))) = make_uint4(0,0,0,0);
        // V natural rows: sV[key][dim], 64B rows (24 dims + 8 zero pad), SW64
        const float4* vp = reinterpret_cast<const float4*>(
            qkv + (size_t)(win*128 + r)*576 + h*24 + 384);
        uint32_t v[12];
        #pragma unroll
        for (int i = 0; i < 6; i++) {
            float4 a = vp[i];
            v[2*i]   = bf2(a.x, a.y);
            v[2*i+1] = bf2(a.z, a.w);
        }
        uint8_t* vb = smp + 32768;
        *reinterpret_cast<uint4*>(vb + SMEM_SWZ64((uint32_t)(r*64 + 0)))  = make_uint4(v[0],v[1],v[2],v[3]);
        *reinterpret_cast<uint4*>(vb + SMEM_SWZ64((uint32_t)(r*64 + 16))) = make_uint4(v[4],v[5],v[6],v[7]);
        *reinterpret_cast<uint4*>(vb + SMEM_SWZ64((uint32_t)(r*64 + 32))) = make_uint4(v[8],v[9],v[10],v[11]);
        *reinterpret_cast<uint4*>(vb + SMEM_SWZ64((uint32_t)(r*64 + 48))) = make_uint4(0,0,0,0);
    } else {
        int r = tid - 128;
        const float4* kp = reinterpret_cast<const float4*>(
            qkv + (size_t)(win*128 + r)*576 + h*24 + 192);
        uint32_t w[12];
        #pragma unroll
        for (int i = 0; i < 6; i++) {
            float4 a = kp[i];
            w[2*i]   = bf2(a.x, a.y);
            w[2*i+1] = bf2(a.z, a.w);
        }
        uint8_t* kbp = smp + 16384;
        *reinterpret_cast<uint4*>(kbp + SMEM_SWZ((uint32_t)(r*128 + 0)))  = make_uint4(w[0],w[1],w[2],w[3]);
        *reinterpret_cast<uint4*>(kbp + SMEM_SWZ((uint32_t)(r*128 + 16))) = make_uint4(w[4],w[5],w[6],w[7]);
        *reinterpret_cast<uint4*>(kbp + SMEM_SWZ((uint32_t)(r*128 + 32))) = make_uint4(w[8],w[9],w[10],w[11]);
        *reinterpret_cast<uint4*>(kbp + SMEM_SWZ((uint32_t)(r*128 + 48))) = make_uint4(0,0,0,0);
    }
    __syncthreads();

    int g = lane >> 3, l7 = lane & 7;
    int qr = lane >> 2, qc = (lane & 3) * 2;
    int r0 = wid * 16;

    constexpr int NP = MUT ? 4 : 8;          // K-column tiles per warp
    int colbase = MUT ? (r0 & 64) : 0;       // MUT: only same-half columns

    // ---------- S = Q @ K^T : warp owns rows r0..r0+15 ----------
    float c[2*NP][4] = {};
    #pragma unroll
    for (int ks = 0; ks < 2; ks++) {
        uint32_t a0, a1, a2, a3;
        int ar = r0 + ((g & 1) << 3) + l7;
        int akb = ks*32 + ((g >> 1) << 4);
        ldsm_x4(a0, a1, a2, a3, sQ + SMEM_SWZ((uint32_t)(ar*128 + akb)));
        #pragma unroll
        for (int np = 0; np < NP; np++) {
            int r = colbase + np*16 + ((g >> 1) << 3) + l7;
            int kb = ks*32 + ((g & 1) << 4);
            uint32_t b0, b1, b2, b3;
            ldsm_x4(b0, b1, b2, b3, sK + SMEM_SWZ((uint32_t)(r*128 + kb)));
            mma16816(c[2*np],   a0, a1, a2, a3, b0, b1);
            mma16816(c[2*np+1], a0, a1, a2, a3, b2, b3);
        }
    }

    // ---------- softmax in-register, pack P to A-fragments ----------
    const __nv_bfloat16* bm = g_bmh + ((size_t)(sel*8 + h))*16384;
    const __nv_bfloat16* mm = g_mmh + (size_t)sel*4096;
    int row0q = r0 + qr, row1q = r0 + 8 + qr;
    float sum0 = 0.f, sum1 = 0.f;
    uint32_t pa[NP][4];
    #pragma unroll
    for (int nj = 0; nj < 2*NP; nj++) {
        int col = colbase + nj*8 + qc;
        float bx0, by0, bx1, by1;
        if (MUT) {
            float2 m0 = __bfloat1622float2(*reinterpret_cast<const __nv_bfloat162*>(
                mm + (row0q & 63)*64 + (col & 63)));
            float2 m1 = __bfloat1622float2(*reinterpret_cast<const __nv_bfloat162*>(
                mm + (row1q & 63)*64 + (col & 63)));
            bx0 = m0.x; by0 = m0.y;
            bx1 = m1.x; by1 = m1.y;
        } else {
            float2 b0 = __bfloat1622float2(*reinterpret_cast<const __nv_bfloat162*>(
                bm + row0q*128 + col));
            float2 b1 = __bfloat1622float2(*reinterpret_cast<const __nv_bfloat162*>(
                bm + row1q*128 + col));
            bx0 = b0.x; by0 = b0.y;
            bx1 = b1.x; by1 = b1.y;
        }
        float p00 = __expf(c[nj][0] + bx0);
        float p01 = __expf(c[nj][1] + by0);
        float p10 = __expf(c[nj][2] + bx1);
        float p11 = __expf(c[nj][3] + by1);
        sum0 += p00 + p01;
        sum1 += p10 + p11;
        int kt = nj >> 1, half = (nj & 1) << 1;
        pa[kt][half + 0] = bf2(p00, p01);
        pa[kt][half + 1] = bf2(p10, p11);
    }
    sum0 += __shfl_xor_sync(0xffffffffu, sum0, 1);
    sum0 += __shfl_xor_sync(0xffffffffu, sum0, 2);
    sum1 += __shfl_xor_sync(0xffffffffu, sum1, 1);
    sum1 += __shfl_xor_sync(0xffffffffu, sum1, 2);

    // ---------- O = P @ V : A from registers, B via ldmatrix.trans on sV ----
    float o[3][4] = {};
    #pragma unroll
    for (int kt = 0; kt < NP; kt++) {
        int krow = colbase + kt*16 + ((g & 1) << 3) + l7;
        uint32_t b0, b1, b2, b3, d0, d1, d2, d3;
        ldsm_x4_t(b0, b1, b2, b3, sV + SMEM_SWZ64((uint32_t)(krow*64 + ((g >> 1) << 4))));
        ldsm_x4_t(d0, d1, d2, d3, sV + SMEM_SWZ64((uint32_t)(krow*64 + 32 + ((g >> 1) << 4))));
        mma16816(o[0], pa[kt][0], pa[kt][1], pa[kt][2], pa[kt][3], b0, b1);
        mma16816(o[1], pa[kt][0], pa[kt][1], pa[kt][2], pa[kt][3], b2, b3);
        mma16816(o[2], pa[kt][0], pa[kt][1], pa[kt][2], pa[kt][3], d0, d1);
    }

    // ---------- epilogue: divide by register row sums, store bf16 ----------
    int coff = MUT ? 0 : 192;
    float inv0 = 1.f / sum0, inv1 = 1.f / sum1;
    #pragma unroll
    for (int hh = 0; hh < 2; hh++) {
        int row = r0 + hh*8 + qr;
        float inv = hh ? inv1 : inv0;
        __nv_bfloat16* ob = g_xout_bf + (size_t)(win*128 + row)*384 + coff + h*24;
        #pragma unroll
        for (int nj = 0; nj < 3; nj++) {
            float v0 = o[nj][2*hh]   * inv;
            float v1 = o[nj][2*hh+1] * inv;
            *reinterpret_cast<uint32_t*>(ob + nj*8 + qc) = bf2(v0, v1);
        }
    }
}

// ---- shared mode-0 GEMM core: C fp32 = A @ Bt^T + bias ---------------------
__device__ __forceinline__ void gemm_core0(
        const __nv_bfloat16* __restrict__ A,
        const __nv_bfloat16* __restrict__ Bt,
        const float* __restrict__ bias,
        float* __restrict__ Cf, int K, int ldC, uint8_t* dyn_raw) {
    int tid = threadIdx.x, wid = tid >> 5, lane = tid & 31;
    int wm = wid >> 1, wn = wid & 1;
    int row0 = blockIdx.x * 128, col0 = blockIdx.y * 64;

    uint32_t aBase = (smem_u32(dyn_raw) + 1023u) & ~1023u;
    uint32_t bBase = aBase + 32768;

    int srow = tid >> 3, c16 = tid & 7;
    const __nv_bfloat16* arp[4]; uint32_t aOff[4];
    #pragma unroll
    for (int i = 0; i < 4; i++) {
        int r = i*32 + srow;
        aOff[i] = SMEM_SWZ((uint32_t)(r*128 + c16*16));
        arp[i] = A + (size_t)(row0 + r)*K + c16*8;
    }
    const __nv_bfloat16* brp[2]; uint32_t bOff[2];
    #pragma unroll
    for (int i = 0; i < 2; i++) {
        int r = i*32 + srow;
        bOff[i] = SMEM_SWZ((uint32_t)(r*128 + c16*16));
        brp[i] = Bt + (size_t)(col0 + r)*K + c16*8;
    }

    float c[2][4][4] = {};
    int nch = K >> 6;

    #pragma unroll
    for (int i = 0; i < 4; i++) cp16(aBase + aOff[i], arp[i], true);
    #pragma unroll
    for (int i = 0; i < 2; i++) cp16(bBase + bOff[i], brp[i], true);
    CP_COMMIT();

    for (int ic = 0; ic < nch; ic++) {
        if (ic + 1 < nch) {
            int buf = (ic + 1) & 1, kc = (ic + 1) << 6;
            #pragma unroll
            for (int i = 0; i < 4; i++)
                cp16(aBase + buf*16384 + aOff[i], arp[i] + kc, true);
            #pragma unroll
            for (int i = 0; i < 2; i++)
                cp16(bBase + buf*8192 + bOff[i], brp[i] + kc, true);
            CP_COMMIT();
            CP_WAIT1();
        } else {
            CP_WAIT0();
        }
        __syncthreads();
        mma_tile(aBase + (ic & 1)*16384, bBase + (ic & 1)*8192, c, wm, wn, lane);
        __syncthreads();
    }

    int qr = lane >> 2, qc = (lane & 3) * 2;
    #pragma unroll
    for (int mi = 0; mi < 2; mi++) {
        #pragma unroll
        for (int h = 0; h < 2; h++) {
            int lr = wm*32 + mi*16 + h*8 + qr;
            #pragma unroll
            for (int nj = 0; nj < 4; nj++) {
                int col = col0 + wn*32 + nj*8 + qc;
                size_t crow = (size_t)(row0 + lr)*ldC + col;
                *reinterpret_cast<float2*>(Cf + crow) =
                    make_float2(c[mi][nj][2*h] + bias[col],
                                c[mi][nj][2*h+1] + bias[col+1]);
            }
        }
    }
}

// ---- merged QKV GEMM: z=0 self, z=1 mutual ----------------------------------
__global__ __launch_bounds__(256, 3) void gemm_qkv(const float* __restrict__ qsb,
                                                   const float* __restrict__ qmb) {
    extern __shared__ uint8_t dyn_raw[];
    if (blockIdx.z == 0)
        gemm_core0(g_xw_bf, g_wt_qs, qsb, g_qkv_s, 192, 576, dyn_raw);
    else
        gemm_core0(g_xm_bf, g_wt_qm, qmb, g_qkv_m, 192, 576, dyn_raw);
}

// ---- proj GEMM ---------------------------------------------------------------
__global__ __launch_bounds__(256, 3) void gemm_proj(
        const __nv_bfloat16* __restrict__ A, const __nv_bfloat16* __restrict__ Bt,
        const float* __restrict__ bias, float* __restrict__ Cf, int K, int ldC) {
    extern __shared__ uint8_t dyn_raw[];
    gemm_core0(A, Bt, bias, Cf, K, ldC, dyn_raw);
}

// ======= MoE FC1: gather + gelu -> g_hbuf, wide 128x128 tile, K=192 =========
__global__ __launch_bounds__(256) void gemm_moe1(const float* __restrict__ b1) {
    extern __shared__ uint8_t dyn_raw[];
    __shared__ int s_tok[128];
    int tid = threadIdx.x, wid = tid >> 5, lane = tid & 31;
    int wm = wid >> 1, wn = wid & 1;
    int row0 = blockIdx.x * 128, col0 = blockIdx.y * 128;
    int e = blockIdx.z;
    int cnt = g_cnt[e];
    if (row0 >= cnt) return;
    const __nv_bfloat16* W1te = g_wt_w1 + (size_t)e*73728;
    const float* b1e = b1 + e*384;

    if (tid < 128) {
        int slot = row0 + tid;
        s_tok[tid] = (slot < cnt) ? g_gidx[e*TTOK + slot] : -1;
    }
    __syncthreads();

    uint32_t aBase = (smem_u32(dyn_raw) + 1023u) & ~1023u;
    uint32_t bBase = aBase + 32768;

    int srow = tid >> 3, c16 = tid & 7;
    const __nv_bfloat16* arp[4]; bool av[4]; uint32_t off[4];
    const __nv_bfloat16* brp[4];
    #pragma unroll
    for (int i = 0; i < 4; i++) {
        int r = i*32 + srow;
        off[i] = SMEM_SWZ((uint32_t)(r*128 + c16*16));
        int tk = s_tok[r];
        av[i] = (tk >= 0);
        arp[i] = g_xn2_bf + (size_t)(av[i] ? tk : 0)*192 + c16*8;
        brp[i] = W1te + (size_t)(col0 + r)*192 + c16*8;
    }

    float c[2][8][4] = {};

    #pragma unroll
    for (int i = 0; i < 4; i++) cp16(aBase + off[i], arp[i], av[i]);
    #pragma unroll
    for (int i = 0; i < 4; i++) cp16(bBase + off[i], brp[i], true);
    CP_COMMIT();

    for (int ic = 0; ic < 3; ic++) {
        if (ic + 1 < 3) {
            int buf = (ic + 1) & 1, kc = (ic + 1) << 6;
            #pragma unroll
            for (int i = 0; i < 4; i++)
                cp16(aBase + buf*16384 + off[i], arp[i] + kc, av[i]);
            #pragma unroll
            for (int i = 0; i < 4; i++)
                cp16(bBase + buf*16384 + off[i], brp[i] + kc, true);
            CP_COMMIT();
            CP_WAIT1();
        } else {
            CP_WAIT0();
        }
        __syncthreads();
        mma_tile_w(aBase + (ic & 1)*16384, bBase + (ic & 1)*16384, c, wm, wn, lane);
        __syncthreads();
    }

    int qr = lane >> 2, qc = (lane & 3) * 2;
    #pragma unroll
    for (int mi = 0; mi < 2; mi++) {
        #pragma unroll
        for (int h = 0; h < 2; h++) {
            int lr = wm*32 + mi*16 + h*8 + qr;
            if (s_tok[lr] >= 0) {
                size_t hrow = ((size_t)e*TTOK + row0 + lr)*384;
                #pragma unroll
                for (int nj = 0; nj < 8; nj++) {
                    int col = col0 + wn*64 + nj*8 + qc;
                    float h0 = c[mi][nj][2*h]   + b1e[col];
                    float h1 = c[mi][nj][2*h+1] + b1e[col+1];
                    h0 = h0 * normcdff(h0);
                    h1 = h1 * normcdff(h1);
                    *reinterpret_cast<uint32_t*>(g_hbuf + hrow + col) = bf2(h0, h1);
                }
            }
        }
    }
}

// ======= MoE FC2: weighted scatter -> contrib buffers, K=384 ================
__global__ __launch_bounds__(256, 3) void gemm_moe2(const float* __restrict__ b2) {
    extern __shared__ uint8_t dyn_raw[];
    __shared__ int s_tok[128]; __shared__ float s_wgt[128]; __shared__ int s_rnk[128];

    int tid = threadIdx.x, wid = tid >> 5, lane = tid & 31;
    int wm = wid >> 1, wn = wid & 1;
    int row0 = blockIdx.x * 128, col0 = blockIdx.y * 64;
    int e = blockIdx.z;
    int cnt = g_cnt[e];
    if (row0 >= cnt) return;
    const __nv_bfloat16* Bte = g_wt_w2 + (size_t)e*73728;
    const float* be = b2 + e*192;
    const __nv_bfloat16* Ae = g_hbuf + (size_t)e*TTOK*384;

    if (tid < 128) {
        int slot = row0 + tid;
        if (slot < cnt) {
            s_tok[tid] = g_gidx[e*TTOK + slot];
            s_wgt[tid] = g_gw[e*TTOK + slot];
            s_rnk[tid] = g_grank[e*TTOK + slot];
        } else s_tok[tid] = -1;
    }
    __syncthreads();

    uint32_t aBase = (smem_u32(dyn_raw) + 1023u) & ~1023u;
    uint32_t bBase = aBase + 32768;

    int srow = tid >> 3, c16 = tid & 7;
    const __nv_bfloat16* arp[4]; bool av[4]; uint32_t aOff[4];
    #pragma unroll
    for (int i = 0; i < 4; i++) {
        int r = i*32 + srow;
        aOff[i] = SMEM_SWZ((uint32_t)(r*128 + c16*16));
        av[i] = (row0 + r < cnt);
        arp[i] = Ae + (size_t)(av[i] ? (row0 + r) : 0)*384 + c16*8;
    }
    const __nv_bfloat16* brp[2]; uint32_t bOff[2];
    #pragma unroll
    for (int i = 0; i < 2; i++) {
        int r = i*32 + srow;
        bOff[i] = SMEM_SWZ((uint32_t)(r*128 + c16*16));
        brp[i] = Bte + (size_t)(col0 + r)*384 + c16*8;
    }

    float c[2][4][4] = {};

    #pragma unroll
    for (int i = 0; i < 4; i++) cp16(aBase + aOff[i], arp[i], av[i]);
    #pragma unroll
    for (int i = 0; i < 2; i++) cp16(bBase + bOff[i], brp[i], true);
    CP_COMMIT();

    for (int ic = 0; ic < 6; ic++) {
        if (ic + 1 < 6) {
            int buf = (ic + 1) & 1, kc = (ic + 1) << 6;
            #pragma unroll
            for (int i = 0; i < 4; i++)
                cp16(aBase + buf*16384 + aOff[i], arp[i] + kc, av[i]);
            #pragma unroll
            for (int i = 0; i < 2; i++)
                cp16(bBase + buf*8192 + bOff[i], brp[i] + kc, true);
            CP_COMMIT();
            CP_WAIT1();
        } else {
            CP_WAIT0();
        }
        __syncthreads();
        mma_tile(aBase + (ic & 1)*16384, bBase + (ic & 1)*8192, c, wm, wn, lane);
        __syncthreads();
    }

    int qr = lane >> 2, qc = (lane & 3) * 2;
    #pragma unroll
    for (int mi = 0; mi < 2; mi++) {
        #pragma unroll
        for (int h = 0; h < 2; h++) {
            int lr = wm*32 + mi*16 + h*8 + qr;
            int tk = s_tok[lr];
            if (tk >= 0) {
                float w = s_wgt[lr];
                float* dst = (s_rnk[lr] == 0) ? g_contrib0 : g_contrib1;
                #pragma unroll
                for (int nj = 0; nj < 4; nj++) {
                    int col = col0 + wn*32 + nj*8 + qc;
                    *reinterpret_cast<float2*>(dst + (size_t)tk*192 + col) =
                        make_float2(w*(c[mi][nj][2*h]   + be[col]),
                                    w*(c[mi][nj][2*h+1] + be[col+1]));
                }
            }
        }
    }
}

// ---- merged prep: transpose (0-359) | bmh (360-423) | mmh (424-431) | pos (432)
__global__ __launch_bounds__(256) void k_prep_all(
        const float* __restrict__ qs, const float* __restrict__ qm,
        const float* __restrict__ pw, const float* __restrict__ W1,
        const float* __restrict__ W2, const float* __restrict__ rpb,
        const float* __restrict__ mask) {
    __shared__ float tile[64][65];
    int bid = blockIdx.x;
    if (bid < 360) {
        const float* src; __nv_bfloat16* dst; int K, N, tk, tn;
        if (bid < 27)       { src = qs; dst = g_wt_qs; K = 192; N = 576; tk = bid/9; tn = bid%9; }
        else if (bid < 54)  { int j = bid-27; src = qm; dst = g_wt_qm; K = 192; N = 576; tk = j/9; tn = j%9; }
        else if (bid < 72)  { int j = bid-54; src = pw; dst = g_wt_p;  K = 384; N = 192; tk = j/3; tn = j%3; }
        else if (bid < 216) { int j = bid-72;  int e = j/18; j %= 18;
                              src = W1 + (size_t)e*73728; dst = g_wt_w1 + (size_t)e*73728;
                              K = 192; N = 384; tk = j/6; tn = j%6; }
        else                { int j = bid-216; int e = j/18; j %= 18;
                              src = W2 + (size_t)e*73728; dst = g_wt_w2 + (size_t)e*73728;
                              K = 384; N = 192; tk = j/3; tn = j%3; }
        int rr = threadIdx.x >> 6, cc = threadIdx.x & 63;
        #pragma unroll 4
        for (int i = 0; i < 16; i++) {
            int r = rr + 4*i;
            tile[r][cc] = src[(size_t)(tk*64 + r)*N + tn*64 + cc];
        }
        __syncthreads();
        #pragma unroll 4
        for (int i = 0; i < 16; i++) {
            int r = rr + 4*i;
            dst[(size_t)(tn*64 + r)*K + tk*64 + cc] = __float2bfloat16_rn(tile[cc][r]);
        }
    } else if (bid < 424) {
        // combined mask+bias bf16 table: one block per (sel, h); 8 distinct masks
        int idx = bid - 360;
        int sel = idx >> 3, h = idx & 7;
        int mwr = ((sel & 4) ? 2 : 0)*64 + ((sel & 2) ? 7 : 0)*8 + ((sel & 1) ? 7 : 0);
        const float* mrow = mask + (size_t)mwr*16384;
        __nv_bfloat16* dst = g_bmh + (size_t)idx*16384;
        for (int e = threadIdx.x; e < 8192; e += 256) {
            int q = e >> 6, k2 = (e & 63)*2;
            int dn = q >> 6, hn = (q >> 3) & 7, wn = q & 7;
            float v[2];
            #pragma unroll
            for (int j = 0; j < 2; j++) {
                int k = k2 + j;
                int dm = k >> 6, hm = (k >> 3) & 7, wm = k & 7;
                int rp = (dn - dm + 1)*225 + (hn - hm + 7)*15 + (wn - wm + 7);
                v[j] = mrow[q*128 + k] + rpb[rp*8 + h];
            }
            *reinterpret_cast<uint32_t*>(dst + q*128 + k2) = bf2(v[0], v[1]);
        }
    } else if (bid < 432) {
        // mask quadrant bf16: one block per sel
        int sel = bid - 424;
        int mwr = ((sel & 4) ? 2 : 0)*64 + ((sel & 2) ? 7 : 0)*8 + ((sel & 1) ? 7 : 0);
        const float* mrow = mask + (size_t)mwr*16384;
        __nv_bfloat16* dst = g_mmh + (size_t)sel*4096;
        for (int e = threadIdx.x; e < 2048; e += 256) {
            int q = e >> 5, k2 = (e & 31)*2;
            float v0 = mrow[q*128 + k2], v1 = mrow[q*128 + k2 + 1];
            *reinterpret_cast<uint32_t*>(dst + q*64 + k2) = bf2(v0, v1);
        }
    } else {
        int c = threadIdx.x;
        if (c >= 192) return;
        if (c < 8) g_cnt[c] = 0;
        const float TWO_PI = 6.283185307179586f;
        const float denom = 8.0f + 1e-6f;
        int f = (c < 96) ? c : c - 96;
        float expo = (float)(f & ~1) / 96.0f;
        float dt = powf(10000.0f, expo);
        for (int n = 0; n < 64; n++) {
            int i = n >> 3, j = n & 7;
            float base = (c < 96) ? (float)(i + 1) : (float)(j + 1);
            float v = base / denom * TWO_PI / dt;
            g_pos[n*192 + c] = (f & 1) ? cosf(v) : sinf(v);
        }
    }
}

// ---------------- LN1 + roll + window partition -> bf16 (warp per token) -----
__global__ __launch_bounds__(256) void ln_partition(const float* __restrict__ x,
                             const float* __restrict__ w1,
                             const float* __restrict__ b1) {
    int t = (blockIdx.x*blockDim.x + threadIdx.x) >> 5;
    int lane = threadIdx.x & 31;
    int win = t >> 7, n = t & 127;
    int b_  = win / 192; int rem = win % 192;
    int dd  = rem / 64;  int rem2 = rem % 64;
    int hh  = rem2 >> 3; int ww = rem2 & 7;
    int wd  = n >> 6, wh = (n >> 3) & 7, wwp = n & 7;
    int ds = dd*2 + wd, hs = hh*8 + wh, ws = ww*8 + wwp;
    int d = ds + 1; if (d >= 6) d -= 6;
    int h = (hs + 4) & 63;
    int w = (ws + 4) & 63;
    const float* xr = x + (size_t)(((b_*6 + d)*64 + h)*64 + w)*192;
    float v[6];
    float s1 = 0.f, s2 = 0.f;
    #pragma unroll
    for (int k = 0; k < 6; k++) {
        v[k] = xr[lane + 32*k];
        s1 += v[k]; s2 += v[k]*v[k];
    }
    s1 = warpsum_all(s1); s2 = warpsum_all(s2);
    float mu  = s1 * (1.f/192.f);
    float var = s2 * (1.f/192.f) - mu*mu;
    float rstd = rsqrtf(var + 1e-5f);
    const float* pr = g_pos + (n & 63)*192;
    #pragma unroll
    for (int k = 0; k < 6; k++) {
        int cc = lane + 32*k;
        float y = (v[k] - mu) * rstd * w1[cc] + b1[cc];
        g_xw_bf[(size_t)t*192 + cc] = __float2bfloat16_rn(y);
        g_xm_bf[(size_t)t*192 + cc] = __float2bfloat16_rn(y + pr[cc]);
    }
}

// --------- residual (writes out directly) + LN2 + gate top-2 -----------------
__global__ __launch_bounds__(256) void resid_gate(const float* __restrict__ x,
                           const float* __restrict__ n2w, const float* __restrict__ n2b,
                           const float* __restrict__ gw,  const float* __restrict__ gb,
                           float* __restrict__ out) {
    __shared__ float s_gw[8*192];
    for (int i = threadIdx.x; i < 1536; i += 256) {
        int j = i / 192, cc = i % 192;
        s_gw[i] = gw[cc*8 + j];
    }
    __syncthreads();
    int t = (blockIdx.x*blockDim.x + threadIdx.x) >> 5;
    int lane = threadIdx.x & 31;
    int b_ = t / 24576; int rrem = t % 24576;
    int d  = rrem / 4096; int r2 = rrem % 4096;
    int hh_ = r2 / 64; int ww_ = r2 % 64;
    int ds = d - 1; if (ds < 0) ds += 6;
    int hs = (hh_ + 60) & 63;
    int ws = (ww_ + 60) & 63;
    int dd = ds >> 1, wd = ds & 1;
    int hblk = hs >> 3, wh = hs & 7;
    int wblk = ws >> 3, wwp = ws & 7;
    int win = ((b_*3 + dd)*8 + hblk)*8 + wblk;
    int n = wd*64 + wh*8 + wwp;
    const float* ar = g_attnbuf + (size_t)(win*128 + n)*192;
    const float* xr = x + (size_t)t*192;
    float v[6];
    float s1 = 0.f, s2 = 0.f;
    #pragma unroll
    for (int k = 0; k < 6; k++) {
        int cc = lane + 32*k;
        v[k] = xr[cc] + ar[cc];
        out[(size_t)t*192 + cc] = v[k];
        s1 += v[k]; s2 += v[k]*v[k];
    }
    s1 = warpsum_all(s1); s2 = warpsum_all(s2);
    float mu  = s1 * (1.f/192.f);
    float var = s2 * (1.f/192.f) - mu*mu;
    float rstd = rsqrtf(var + 1e-5f);
    float g[8] = {};
    #pragma unroll
    for (int k = 0; k < 6; k++) {
        int cc = lane + 32*k;
        float xn = (v[k] - mu) * rstd * n2w[cc] + n2b[cc];
        g_xn2_bf[(size_t)t*192 + cc] = __float2bfloat16_rn(xn);
        #pragma unroll
        for (int j = 0; j < 8; j++) g[j] = fmaf(xn, s_gw[j*192 + cc], g[j]);
    }
    #pragma unroll
    for (int j = 0; j < 8; j++) g[j] = warpsum_all(g[j]);
    if (lane == 0) {
        float L[8];
        #pragma unroll
        for (int j = 0; j < 8; j++) L[j] = g[j] + gb[j];
        int e0 = 0;
        #pragma unroll
        for (int j = 1; j < 8; j++) if (L[j] > L[e0]) e0 = j;
        int e1 = (e0 == 0) ? 1 : 0;
        #pragma unroll
        for (int j = 0; j < 8; j++) if (j != e0 && L[j] > L[e1]) e1 = j;
        float w0 = 1.f / (1.f + __expf(L[e1] - L[e0]));
        float w1 = 1.f - w0;
        int p0 = atomicAdd(&g_cnt[e0], 1);
        g_gidx[e0*TTOK + p0] = t; g_gw[e0*TTOK + p0] = w0; g_grank[e0*TTOK + p0] = 0;
        int p1 = atomicAdd(&g_cnt[e1], 1);
        g_gidx[e1*TTOK + p1] = t; g_gw[e1*TTOK + p1] = w1; g_grank[e1*TTOK + p1] = 1;
    }
}

// ---------------- finalize: out += contrib0 + contrib1 -----------------------
__global__ void finalize(float* __restrict__ out) {
    int i = blockIdx.x*blockDim.x + threadIdx.x;
    if (i < TTOK*48) {
        float4 a  = reinterpret_cast<const float4*>(out)[i];
        float4 c0 = reinterpret_cast<const float4*>(g_contrib0)[i];
        float4 c1 = reinterpret_cast<const float4*>(g_contrib1)[i];
        reinterpret_cast<float4*>(out)[i] =
            make_float4(a.x + c0.x + c1.x, a.y + c0.y + c1.y,
                        a.z + c0.z + c1.z, a.w + c0.w + c1.w);
    }
}

// ---------------- host launcher -----------------------------------------------
extern "C" void kernel_launch(void* const* d_in, const int* in_sizes, int n_in,
                              void* d_out, int out_size) {
    const float* x    = (const float*)d_in[0];
    const float* mask = (const float*)d_in[1];
    const float* n1w  = (const float*)d_in[2];
    const float* n1b  = (const float*)d_in[3];
    const float* qsw  = (const float*)d_in[4];
    const float* qsb  = (const float*)d_in[5];
    const float* qmw  = (const float*)d_in[6];
    const float* qmb  = (const float*)d_in[7];
    const float* rpb  = (const float*)d_in[8];
    const float* pw   = (const float*)d_in[9];
    const float* pb   = (const float*)d_in[10];
    const float* n2w  = (const float*)d_in[11];
    const float* n2b  = (const float*)d_in[12];
    const float* gw   = (const float*)d_in[13];
    const float* gb   = (const float*)d_in[14];
    const float* W1   = (const float*)d_in[15];
    const float* b1   = (const float*)d_in[16];
    const float* W2   = (const float*)d_in[17];
    const float* b2   = (const float*)d_in[18];
    float* out = (float*)d_out;

    const int DSMEM  = 50176;   // 48KB + align pad
    const int DSMEM1 = 66560;   // 64KB + align pad (wide FC1)
    const int ASMEM  = 41984;   // attn: 40KB tiles + align pad
    cudaFuncSetAttribute(gemm_qkv,    cudaFuncAttributeMaxDynamicSharedMemorySize, DSMEM);
    cudaFuncSetAttribute(gemm_proj,   cudaFuncAttributeMaxDynamicSharedMemorySize, DSMEM);
    cudaFuncSetAttribute(gemm_moe1,   cudaFuncAttributeMaxDynamicSharedMemorySize, DSMEM1);
    cudaFuncSetAttribute(gemm_moe2,   cudaFuncAttributeMaxDynamicSharedMemorySize, DSMEM);
    cudaFuncSetAttribute(attn_mma<0>, cudaFuncAttributeMaxDynamicSharedMemorySize, ASMEM);
    cudaFuncSetAttribute(attn_mma<1>, cudaFuncAttributeMaxDynamicSharedMemorySize, ASMEM);

    void *p_xout, *p_attn, *p_wp;
    cudaGetSymbolAddress(&p_xout, g_xout_bf);
    cudaGetSymbolAddress(&p_attn, g_attnbuf);
    cudaGetSymbolAddress(&p_wp,   g_wt_p);

    k_prep_all<<<433, 256>>>(qsw, qmw, pw, W1, W2, rpb, mask);
    ln_partition<<<6144, 256>>>(x, n1w, n1b);
    gemm_qkv<<<dim3(384, 9, 2), 256, DSMEM>>>(qsb, qmb);
    attn_mma<0><<<3072, 256, ASMEM>>>();
    attn_mma<1><<<3072, 256, ASMEM>>>();
    gemm_proj<<<dim3(384, 3), 256, DSMEM>>>((const __nv_bfloat16*)p_xout,
        (const __nv_bfloat16*)p_wp, pb, (float*)p_attn, 384, 192);
    resid_gate<<<6144, 256>>>(x, n2w, n2b, gw, gb, out);
    gemm_moe1<<<dim3(384, 3, 8), 256, DSMEM1>>>(b1);
    gemm_moe2<<<dim3(384, 3, 8), 256, DSMEM>>>(b2);
    finalize<<<9216, 256>>>(out);
}